// round 15
// baseline (speedup 1.0000x reference)
#include <cuda_runtime.h>
#include <cuda_bf16.h>
#include <math.h>
#include <stdint.h>

// ---------------------------------------------------------------------------
// Problem constants
// ---------------------------------------------------------------------------
#define B 4
#define C 64
#define IMGH 48
#define IMGW 48
#define HW 2304                 // 48*48
#define NPIX 589824             // B*C*HW
#define CV 24                   // 3 * (C/8) value columns
#define NSPLIT 2

// first-layer padded cin per branch and weight buffer offsets
#define CIN1P 144
#define CIN2P 32
#define CIN3P 16
#define W1OFF 0
#define W2OFF (9 * 64 * CIN1P)
#define W3OFF (9 * 64 * (CIN1P + CIN2P))
#define WCTOT (9 * 64 * (CIN1P + CIN2P + CIN3P))

// ---------------------------------------------------------------------------
// Device scratch (no cudaMalloc allowed)
// Features stored PACKED: uint32 = (hi bf16) | (lo bf16 << 16)
// ---------------------------------------------------------------------------
__device__ uint32_t g_fp1[3 * NPIX];            // layer-1 out (br1/br2 packed)
__device__ uint32_t g_fpF[3 * NPIX];            // final features
__device__ float g_pA[3 * NPIX];                // partial sums (conv1-br0 / convm1)
__device__ float g_pB[3 * NPIX];
__device__ float g_pC[NPIX];                    // third partial (conv1 x1 only)
__device__ float g_pD[3 * NPIX];                // convm0 partials
__device__ float g_pE[3 * NPIX];
__device__ float g_r[12 * HW];                  // [3][B][2304]
__device__ uint32_t g_V[B * CV * HW];           // [B][24][HW] packed hi/lo
__device__ float g_O[NSPLIT * 12 * HW * CV];    // [split][3][B][2304][24]
__device__ float g_edge[B * HW];
__device__ float g_scale[9 * 64];
__device__ float g_shift[9 * 64];
// mid-conv weights pre-split to bf16 hi/lo, layout [wi][tap][cout][cin]
__device__ __align__(16) __nv_bfloat16 g_WH[6 * 9 * 64 * 64];
__device__ __align__(16) __nv_bfloat16 g_WL[6 * 9 * 64 * 64];
// first-layer weights, layout [tap][cout][cin_pad] per branch
__device__ __align__(16) __nv_bfloat16 g_WcH[WCTOT];
__device__ __align__(16) __nv_bfloat16 g_WcL[WCTOT];

// ---------------------------------------------------------------------------
// helpers
// ---------------------------------------------------------------------------
__device__ __forceinline__ void ldsm_x4(uint32_t& r0, uint32_t& r1, uint32_t& r2,
                                        uint32_t& r3, uint32_t addr)
{
    asm volatile("ldmatrix.sync.aligned.m8n8.x4.shared.b16 {%0,%1,%2,%3}, [%4];"
                 : "=r"(r0), "=r"(r1), "=r"(r2), "=r"(r3) : "r"(addr));
}

__device__ __forceinline__ void mma16816(float4& d, const uint32_t a[4],
                                         uint32_t b0, uint32_t b1)
{
    asm volatile(
        "mma.sync.aligned.m16n8k16.row.col.f32.bf16.bf16.f32 "
        "{%0,%1,%2,%3}, {%4,%5,%6,%7}, {%8,%9}, {%0,%1,%2,%3};\n"
        : "+f"(d.x), "+f"(d.y), "+f"(d.z), "+f"(d.w)
        : "r"(a[0]), "r"(a[1]), "r"(a[2]), "r"(a[3]), "r"(b0), "r"(b1));
}

__device__ __forceinline__ void mma16808(float4& d, uint32_t a0, uint32_t a1, uint32_t b0)
{
    asm volatile(
        "mma.sync.aligned.m16n8k8.row.col.f32.bf16.bf16.f32 "
        "{%0,%1,%2,%3}, {%4,%5}, {%6}, {%0,%1,%2,%3};\n"
        : "+f"(d.x), "+f"(d.y), "+f"(d.z), "+f"(d.w)
        : "r"(a0), "r"(a1), "r"(b0));
}

__device__ __forceinline__ void split_pair(float x, float y, uint32_t& hi, uint32_t& lo)
{
    __nv_bfloat16 hx = __float2bfloat16(x);
    __nv_bfloat16 hy = __float2bfloat16(y);
    hi = (uint32_t)__bfloat16_as_ushort(hx) | ((uint32_t)__bfloat16_as_ushort(hy) << 16);
    __nv_bfloat16 lx = __float2bfloat16(x - __bfloat162float(hx));
    __nv_bfloat16 ly = __float2bfloat16(y - __bfloat162float(hy));
    lo = (uint32_t)__bfloat16_as_ushort(lx) | ((uint32_t)__bfloat16_as_ushort(ly) << 16);
}

__device__ __forceinline__ uint32_t pack_hl(float y)
{
    __nv_bfloat16 h = __float2bfloat16(y);
    __nv_bfloat16 l = __float2bfloat16(y - __bfloat162float(h));
    return (uint32_t)__bfloat16_as_ushort(h) | ((uint32_t)__bfloat16_as_ushort(l) << 16);
}

__device__ __forceinline__ float unpack_f(uint32_t u)
{
    return __uint_as_float(u << 16) + __uint_as_float(u & 0xFFFF0000u);
}

__device__ __forceinline__ uint32_t ld32(const __nv_bfloat16* p)
{
    return *(const uint32_t*)p;
}

__device__ __forceinline__ float leaky(float y) { return (y > 0.f) ? y : 0.01f * y; }

// ---------------------------------------------------------------------------
// 0) One merged init kernel: BN fold + both weight splits + sobel edge
// ---------------------------------------------------------------------------
__global__ void init_kernel(const float* __restrict__ Wm,
                            const float* __restrict__ Wc1,
                            const float* __restrict__ Wc2,
                            const float* __restrict__ Wc3,
                            const float* __restrict__ x3,
                            const float* __restrict__ bc1, const float* __restrict__ bc2,
                            const float* __restrict__ bc3,
                            const float* __restrict__ bnf_g, const float* __restrict__ bnf_b,
                            const float* __restrict__ bnf_m, const float* __restrict__ bnf_v,
                            const float* __restrict__ bm,
                            const float* __restrict__ bnm_g, const float* __restrict__ bnm_b,
                            const float* __restrict__ bnm_m, const float* __restrict__ bnm_v)
{
    const int bx = blockIdx.x;
    const int t = threadIdx.x;
    if (bx < 864) {
        int idx = bx * 256 + t;
        int cin = idx & 63;
        int r = idx >> 6;
        int cout = r & 63;
        r >>= 6;
        int tap = r % 9;
        int wi = r / 9;
        float x = Wm[((wi * 64 + cout) * 64 + cin) * 9 + tap];
        __nv_bfloat16 h = __float2bfloat16(x);
        g_WH[idx] = h;
        g_WL[idx] = __float2bfloat16(x - __bfloat162float(h));
    } else if (bx < 1296) {
        int idx = (bx - 864) * 256 + t;
        const float* W;
        int cinp, cin_real, rem;
        if (idx < W2OFF)       { W = Wc1; cinp = CIN1P; cin_real = 144; rem = idx - W1OFF; }
        else if (idx < W3OFF)  { W = Wc2; cinp = CIN2P; cin_real = 21;  rem = idx - W2OFF; }
        else                   { W = Wc3; cinp = CIN3P; cin_real = 1;   rem = idx - W3OFF; }
        int cin = rem % cinp;
        int r = rem / cinp;
        int cout = r & 63;
        int tap = r >> 6;
        float x = 0.f;
        if (cin < cin_real)
            x = W[(cout * cin_real + cin) * 9 + tap];
        __nv_bfloat16 h = __float2bfloat16(x);
        g_WcH[idx] = h;
        g_WcL[idx] = __float2bfloat16(x - __bfloat162float(h));
    } else if (bx < 1332) {
        int idx = (bx - 1296) * 256 + t;
        if (idx >= B * HW) return;
        int b = idx / HW, p = idx % HW;
        int h = p / IMGW, w = p % IMGW;
        const float* X = x3 + b * HW;
        float ex = 0.f, ey = 0.f;
        const float KX[9] = {-1.f, 0.f, 1.f, -2.f, 0.f, 2.f, -1.f, 0.f, 1.f};
        const float KY[9] = {-1.f, -2.f, -1.f, 0.f, 0.f, 0.f, 1.f, 2.f, 1.f};
#pragma unroll
        for (int kh = 0; kh < 3; kh++) {
            int gh = h + kh - 1;
            if (gh < 0 || gh >= IMGH) continue;
#pragma unroll
            for (int kw = 0; kw < 3; kw++) {
                int gw = w + kw - 1;
                if (gw < 0 || gw >= IMGW) continue;
                float xv = X[gh * IMGW + gw];
                ex += xv * KX[kh * 3 + kw];
                ey += xv * KY[kh * 3 + kw];
            }
        }
        g_edge[idx] = sqrtf(ex * ex + ey * ey);
    } else {
        int idx = (bx - 1332) * 256 + t;
        if (idx >= 576) return;
        int bi = idx >> 6, c = idx & 63;
        float bias, g, be, m, v;
        if (bi < 3) {
            bias = (bi == 0) ? bc1[c] : (bi == 1) ? bc2[c] : bc3[c];
            g = bnf_g[bi * 64 + c]; be = bnf_b[bi * 64 + c];
            m = bnf_m[bi * 64 + c]; v = bnf_v[bi * 64 + c];
        } else {
            int r = bi - 3;
            bias = bm[r * 64 + c];
            g = bnm_g[r * 64 + c]; be = bnm_b[r * 64 + c];
            m = bnm_m[r * 64 + c]; v = bnm_v[r * 64 + c];
        }
        float s = g * rsqrtf(v + 1e-5f);
        g_scale[idx] = s;
        g_shift[idx] = (bias - m) * s + be;
    }
}

// ---------------------------------------------------------------------------
// 2) Tensor-core 3x3 conv body (m32 tile, ldmatrix A, STS.128 weights).
//    Input MODE: 0=fp32 raw input (conv1), 1=packed u32, 2=sum3+BN, 3=sum2+BN.
//    RAW_OUT=true -> fp32 partial output; false -> fused BN+leaky+packed.
// ---------------------------------------------------------------------------
#define CINP 18
#define WSTR 24
#define CS_IMG_H 0
#define CS_IMG_L 5400                        // 300 * 18
#define CS_W_H   10800
#define CS_W_L   (10800 + 9 * 64 * WSTR)     // 24624
#define CS_ELEMS (CS_W_L + 9 * 64 * WSTR)    // 38448
#define CONV_SMEM_BYTES (CS_ELEMS * 2)       // 76896

template<int MODE, bool RAW_OUT>
__device__ __forceinline__ void conv_tc_body(const void* __restrict__ in0,
                                             const void* __restrict__ in1,
                                             const void* __restrict__ in2,
                                             const __nv_bfloat16* __restrict__ WHsrc,
                                             const __nv_bfloat16* __restrict__ WLsrc,
                                             int cin_stride, int cin_count, int cin_real,
                                             int bn_stage_base,   // g_scale offset for staging BN
                                             int bn_out,
                                             void* __restrict__ outv)
{
    extern __shared__ __align__(16) char csraw[];
    __nv_bfloat16* cs = (__nv_bfloat16*)csraw;
    __nv_bfloat16* imgH = cs + CS_IMG_H;
    __nv_bfloat16* imgL = cs + CS_IMG_L;
    __nv_bfloat16* wsH  = cs + CS_W_H;
    __nv_bfloat16* wsL  = cs + CS_W_L;
    const uint32_t sbase = (uint32_t)__cvta_generic_to_shared(csraw);

    const int strip = blockIdx.x;
    const int r0 = strip * 4;
    const int t = threadIdx.x;
    const int lane = t & 31, warp = t >> 5;
    const int wm = warp & 1;
    const int wn = warp >> 1;
    const int gq = lane >> 2, qp = lane & 3;

    float4 acc[2][6];
#pragma unroll
    for (int mt = 0; mt < 2; mt++)
#pragma unroll
        for (int nt = 0; nt < 6; nt++) acc[mt][nt] = make_float4(0.f, 0.f, 0.f, 0.f);

    const int bbase = (wn * 50 + gq) * CINP + 2 * qp;

    const int a_row = (lane & 7) + ((lane >> 3) & 1) * 8;
    const int a_col = ((lane >> 4) & 1) * 8;
    const uint32_t aH0 = sbase + (uint32_t)(CS_W_H + (wm * 32 + a_row) * WSTR + a_col) * 2;
    const uint32_t aL0 = aH0 + (uint32_t)(CS_W_L - CS_W_H) * 2;

    const int p0 = t;
    const int p1 = t + 256;
    const int r_0 = p0 / 50, cc_0 = p0 % 50;
    const int r_1 = p1 / 50, cc_1 = p1 % 50;

    for (int c0 = 0; c0 < cin_count; c0 += 16) {
        __syncthreads();

        // ---- stage image chunk ----
#pragma unroll
        for (int pp = 0; pp < 2; pp++) {
            int pos = pp ? p1 : p0;
            if (pp && p1 >= 300) break;
            int rr = pp ? r_1 : r_0, cc = pp ? cc_1 : cc_0;
            int gr = r0 + rr - 1, gc = cc - 1;
            bool valid = (gr >= 0 && gr < IMGH && gc >= 0 && gc < IMGW);
            int a = pos * CINP;
            size_t goff = (size_t)c0 * HW + gr * IMGW + gc;
            if (MODE == 1) {
                const uint32_t* src = (const uint32_t*)in0 + goff;
                uint32_t u[16];
#pragma unroll
                for (int ci = 0; ci < 16; ci++)
                    u[ci] = valid ? src[ci * HW] : 0u;
#pragma unroll
                for (int ci = 0; ci < 16; ci += 2) {
                    *(uint32_t*)(imgH + a + ci) = __byte_perm(u[ci], u[ci + 1], 0x5410);
                    *(uint32_t*)(imgL + a + ci) = __byte_perm(u[ci], u[ci + 1], 0x7632);
                }
            } else {
                const float* s0 = (const float*)in0 + goff;
                const float* s1 = (const float*)in1 + goff;
                const float* s2 = (const float*)in2 + goff;
                float v[16];
#pragma unroll
                for (int ci = 0; ci < 16; ci++) {
                    if (MODE == 0) {
                        bool ok = valid && (c0 + ci) < cin_real;
                        v[ci] = ok ? s0[ci * HW] : 0.f;
                    } else if (MODE == 2) {
                        v[ci] = valid ? (s0[ci * HW] + s1[ci * HW] + s2[ci * HW]) : 0.f;
                    } else { // MODE 3
                        v[ci] = valid ? (s0[ci * HW] + s1[ci * HW]) : 0.f;
                    }
                }
                if (MODE >= 2) {
#pragma unroll
                    for (int ci = 0; ci < 16; ci++) {
                        float sc = g_scale[bn_stage_base + c0 + ci];
                        float sh = g_shift[bn_stage_base + c0 + ci];
                        v[ci] = valid ? leaky(v[ci] * sc + sh) : 0.f;
                    }
                }
#pragma unroll
                for (int ci = 0; ci < 16; ci += 2) {
                    uint32_t h2, l2;
                    split_pair(v[ci], v[ci + 1], h2, l2);
                    *(uint32_t*)(imgH + a + ci) = h2;
                    *(uint32_t*)(imgL + a + ci) = l2;
                }
            }
        }

        // ---- stage weight chunk: LDG.128 -> STS.128 ----
        for (int q = t; q < 2304; q += 256) {
            int seg = q & 1;
            int plane = (q >> 1) & 1;
            int row = q >> 2;
            const __nv_bfloat16* src = (plane ? WLsrc : WHsrc)
                                       + (size_t)row * cin_stride + c0 + seg * 8;
            __nv_bfloat16* dst = (plane ? wsL : wsH) + row * WSTR + seg * 8;
            *(float4*)dst = *(const float4*)src;
        }
        __syncthreads();

        // ---- 9 tap-GEMMs, k16 each, m32 per warp; A via ldmatrix ----
        for (int tap = 0; tap < 9; tap++) {
            const int tpos = (tap / 3) * 50 + (tap % 3);
            uint32_t Ah[2][4], Al[2][4];
#pragma unroll
            for (int mt = 0; mt < 2; mt++) {
                uint32_t off = (uint32_t)((tap * 64 + mt * 16) * WSTR) * 2;
                ldsm_x4(Ah[mt][0], Ah[mt][1], Ah[mt][2], Ah[mt][3], aH0 + off);
                ldsm_x4(Al[mt][0], Al[mt][1], Al[mt][2], Al[mt][3], aL0 + off);
            }
#pragma unroll
            for (int nt = 0; nt < 6; nt++) {
                int ba = bbase + tpos * CINP + nt * 8 * CINP;
                uint32_t bh0 = ld32(imgH + ba);
                uint32_t bh1 = ld32(imgH + ba + 8);
                uint32_t bl0 = ld32(imgL + ba);
                uint32_t bl1 = ld32(imgL + ba + 8);
#pragma unroll
                for (int mt = 0; mt < 2; mt++) {
                    mma16816(acc[mt][nt], Ah[mt], bh0, bh1);
                    mma16816(acc[mt][nt], Ah[mt], bl0, bl1);
                    mma16816(acc[mt][nt], Al[mt], bh0, bh1);
                }
            }
        }
    }

    // ---- epilogue ----
#pragma unroll
    for (int mt = 0; mt < 2; mt++) {
        int cout0 = wm * 32 + mt * 16 + gq;
        int cout1 = cout0 + 8;
        if (RAW_OUT) {
            float* out = (float*)outv;
#pragma unroll
            for (int nt = 0; nt < 6; nt++) {
                int ocol = nt * 8 + 2 * qp;
                float4 a = acc[mt][nt];
                float* o0 = out + cout0 * HW + (r0 + wn) * IMGW + ocol;
                *(float2*)o0 = make_float2(a.x, a.y);
                *(float2*)(o0 + 8 * HW) = make_float2(a.z, a.w);
            }
        } else {
            uint32_t* out = (uint32_t*)outv;
            float s0 = g_scale[bn_out * 64 + cout0], sh0 = g_shift[bn_out * 64 + cout0];
            float s1 = g_scale[bn_out * 64 + cout1], sh1 = g_shift[bn_out * 64 + cout1];
#pragma unroll
            for (int nt = 0; nt < 6; nt++) {
                int ocol = nt * 8 + 2 * qp;
                float4 a = acc[mt][nt];
                float y0 = leaky(a.x * s0 + sh0);
                float y1 = leaky(a.y * s0 + sh0);
                float y2 = leaky(a.z * s1 + sh1);
                float y3 = leaky(a.w * s1 + sh1);
                uint32_t* o0 = out + cout0 * HW + (r0 + wn) * IMGW + ocol;
                *(uint2*)o0 = make_uint2(pack_hl(y0), pack_hl(y1));
                *(uint2*)(o0 + 8 * HW) = make_uint2(pack_hl(y2), pack_hl(y3));
            }
        }
    }
}

// First layer.  grid (12, 12, 3).
//   br=0 (x1, cin 144): cin-split x3 (z = split), RAW partials -> g_pA/B/C
//   br=1,2: z==0 only, fused BN+pack path -> g_fp1
__global__ __launch_bounds__(256, 2) void conv1_tc_kernel(const float* __restrict__ x1,
                                                          const float* __restrict__ x2,
                                                          const float* __restrict__ x3,
                                                          uint32_t* __restrict__ outbase)
{
    const int zb = blockIdx.y;
    const int b = zb & 3, br = zb >> 2;
    const int z = blockIdx.z;
    if (br == 0) {
        float* part = (z == 0) ? g_pA : (z == 1) ? g_pB : g_pC;
        conv_tc_body<0, true>(x1 + (size_t)b * 144 * HW + (size_t)z * 48 * HW, 0, 0,
                              g_WcH + W1OFF + z * 48, g_WcL + W1OFF + z * 48,
                              CIN1P, 48, 48, 0, 0,
                              part + (size_t)b * C * HW);
    } else if (br == 1) {
        if (z != 0) return;
        conv_tc_body<0, false>(x2 + (size_t)b * 21 * HW, 0, 0,
                               g_WcH + W2OFF, g_WcL + W2OFF,
                               CIN2P, CIN2P, 21, 0, 1,
                               outbase + 1 * NPIX + (size_t)b * C * HW);
    } else {
        if (z != 0) return;
        conv_tc_body<0, false>(x3 + (size_t)b * 1 * HW, 0, 0,
                               g_WcH + W3OFF, g_WcL + W3OFF,
                               CIN3P, CIN3P, 1, 0, 2,
                               outbase + 2 * NPIX + (size_t)b * C * HW);
    }
}

// Mid layer 0: fuses the conv1 fixup into staging.
//   br0 stages sum3(pA,pB,pC)+BN(0); br1/2 stage packed fp1.  -> g_pD/g_pE
__global__ __launch_bounds__(256, 2) void convm0_kernel(const uint32_t* __restrict__ fp1)
{
    const int zb = blockIdx.y;
    const int b = zb & 3, br = zb >> 2;
    const int z = blockIdx.z;
    const int wi = br * 2;
    float* part = (z == 0) ? g_pD : g_pE;
    size_t io = (size_t)br * NPIX + (size_t)b * C * HW + (size_t)z * 32 * HW;
    size_t po = (size_t)b * C * HW + (size_t)z * 32 * HW;   // br0 partials are [B][64][HW]
    if (br == 0) {
        conv_tc_body<2, true>(g_pA + po, g_pB + po, g_pC + po,
                              g_WH + (size_t)wi * 576 * 64 + z * 32,
                              g_WL + (size_t)wi * 576 * 64 + z * 32,
                              64, 32, 32, 0 * 64 + z * 32, 0,
                              part + (size_t)br * NPIX + (size_t)b * C * HW);
    } else {
        conv_tc_body<1, true>(fp1 + io, 0, 0,
                              g_WH + (size_t)wi * 576 * 64 + z * 32,
                              g_WL + (size_t)wi * 576 * 64 + z * 32,
                              64, 32, 32, 0, 0,
                              part + (size_t)br * NPIX + (size_t)b * C * HW);
    }
}

// Mid layer 1: fuses layer-0 fixup into staging (sum2(pD,pE)+BN(3+br*2)).
//   -> g_pA/g_pB partials
__global__ __launch_bounds__(256, 2) void convm1_kernel()
{
    const int zb = blockIdx.y;
    const int b = zb & 3, br = zb >> 2;
    const int z = blockIdx.z;
    const int wi = br * 2 + 1;
    float* part = (z == 0) ? g_pA : g_pB;
    size_t io = (size_t)br * NPIX + (size_t)b * C * HW + (size_t)z * 32 * HW;
    conv_tc_body<3, true>(g_pD + io, g_pE + io, 0,
                          g_WH + (size_t)wi * 576 * 64 + z * 32,
                          g_WL + (size_t)wi * 576 * 64 + z * 32,
                          64, 32, 32, (3 + br * 2) * 64 + z * 32, 0,
                          part + (size_t)br * NPIX + (size_t)b * C * HW);
}

// final fixup: fpF = pack(leaky(BN(pA+pB, 4+br*2)))
__global__ void fixupF_kernel(uint32_t* __restrict__ outbase)
{
    int idx = blockIdx.x * 256 + threadIdx.x;
    float v = g_pA[idx] + g_pB[idx];
    int br = idx / NPIX;
    int rem = idx - br * NPIX;
    int cout = (rem / HW) & 63;
    int bn = 4 + br * 2;
    float y = leaky(v * g_scale[bn * 64 + cout] + g_shift[bn * 64 + cout]);
    outbase[idx] = pack_hl(y);
}

// ---------------------------------------------------------------------------
// 3) squared norms + 1x1 value projection from packed features
// ---------------------------------------------------------------------------
__global__ void valr_kernel(const float* __restrict__ Wv, const float* __restrict__ bv)
{
    __shared__ float wv_s[512];   // [8][64]
    int t = threadIdx.x;
    int j = blockIdx.y, b = blockIdx.z;
    for (int i = t; i < 512; i += 256) wv_s[i] = Wv[i];
    __syncthreads();

    int p = blockIdx.x * 256 + t;
    const uint32_t* F = g_fpF + (j * 4 + b) * C * HW + p;
    float r = 0.f;
    float v[8] = {0, 0, 0, 0, 0, 0, 0, 0};
#pragma unroll 8
    for (int c = 0; c < C; c++) {
        float x = unpack_f(F[c * HW]);
        r += x * x;
#pragma unroll
        for (int cv = 0; cv < 8; cv++) v[cv] += wv_s[cv * 64 + c] * x;
    }
    g_r[(j * 4 + b) * HW + p] = r;
#pragma unroll
    for (int cv = 0; cv < 8; cv++)
        g_V[(b * CV + j * 8 + cv) * HW + p] = pack_hl(v[cv] + bv[cv]);
}

// ---------------------------------------------------------------------------
// 4) Tensor-core fused similarity-attention (bf16 split precision)
// ---------------------------------------------------------------------------
#define TM 128
#define TN 64
#define FSTR 72
#define VSTR 72
#define COLS_PER_SPLIT (HW / NSPLIT)

#define OFF_FRH 0
#define OFF_FRL (OFF_FRH + TM * FSTR * 2)            // 18432
#define OFF_FCH (OFF_FRL + TM * FSTR * 2)            // 36864
#define OFF_FCL (OFF_FCH + TN * FSTR * 2)            // 46080
#define OFF_VSTH (OFF_FCL + TN * FSTR * 2)           // 55296
#define OFF_VSTL (OFF_VSTH + CV * VSTR * 2)          // 58752
#define OFF_RR  (OFF_VSTL + CV * VSTR * 2)           // 62208
#define OFF_RC  (OFF_RR + TM * 4)                    // 62720
#define ATTN_SMEM_BYTES (OFF_RC + TN * 4)            // 62976

__global__ __launch_bounds__(256, 2) void attn_kernel(const float* __restrict__ gammas)
{
    extern __shared__ char sm[];
    unsigned short* FrH = (unsigned short*)(sm + OFF_FRH);
    unsigned short* FrL = (unsigned short*)(sm + OFF_FRL);
    unsigned short* FcH = (unsigned short*)(sm + OFF_FCH);
    unsigned short* FcL = (unsigned short*)(sm + OFF_FCL);
    unsigned short* VsH = (unsigned short*)(sm + OFF_VSTH);
    unsigned short* VsL = (unsigned short*)(sm + OFF_VSTL);
    float* r_r = (float*)(sm + OFF_RR);
    float* r_c = (float*)(sm + OFF_RC);
    uint32_t sb = (uint32_t)__cvta_generic_to_shared(sm);

    const int s    = blockIdx.x & (NSPLIT - 1);
    const int tile = blockIdx.x >> 1;                // log2(NSPLIT)=1
    const int j = blockIdx.y, bb = blockIdx.z;
    const int m0 = tile * TM;
    const int t = threadIdx.x;
    const int warp = t >> 5, lane = t & 31;
    const int mg = warp >> 1, ng = warp & 1;
    const int m0w = mg * 32, n0w = ng * 32;
    const int g = lane >> 2, qp = lane & 3;

    const uint32_t* F = g_fpF + (j * 4 + bb) * C * HW;
    const float* Rj = g_r + (j * 4 + bb) * HW;

    float sg = gammas[j];
    float inv2s = 1.0f / (2.0f * sg * sg);

    for (int idx = t; idx < TM * C; idx += 256) {
        int i = idx & (TM - 1);
        int c = idx >> 7;
        uint32_t u = F[c * HW + m0 + i];
        FrH[i * FSTR + c] = (unsigned short)u;
        FrL[i * FSTR + c] = (unsigned short)(u >> 16);
    }
    if (t < TM) r_r[t] = Rj[m0 + t];
    __syncthreads();

    float rr0[2], rr1[2];
#pragma unroll
    for (int mt = 0; mt < 2; mt++) {
        rr0[mt] = r_r[m0w + mt * 16 + g];
        rr1[mt] = r_r[m0w + mt * 16 + g + 8];
    }

    const int a_r = m0w + (lane & 7) + ((lane >> 3) & 1) * 8;
    const int a_c = ((lane >> 4) & 1) * 8;
    const uint32_t aH0 = sb + OFF_FRH + (uint32_t)(a_r * FSTR + a_c) * 2;
    const uint32_t aL0 = sb + OFF_FRL + (uint32_t)(a_r * FSTR + a_c) * 2;
    const int b_r = n0w + (lane & 7) + ((lane >> 4) & 1) * 8;
    const int b_c = ((lane >> 3) & 1) * 8;
    const uint32_t bH0 = sb + OFF_FCH + (uint32_t)(b_r * FSTR + b_c) * 2;
    const uint32_t bL0 = sb + OFF_FCL + (uint32_t)(b_r * FSTR + b_c) * 2;
    const int vbase = ((lane >> 2) * VSTR + n0w + qp * 2) * 2;

    float4 O[2][3];
#pragma unroll
    for (int mt = 0; mt < 2; mt++)
#pragma unroll
        for (int vt = 0; vt < 3; vt++) O[mt][vt] = make_float4(0.f, 0.f, 0.f, 0.f);

    const int nb0 = s * COLS_PER_SPLIT;
    for (int nb = nb0; nb < nb0 + COLS_PER_SPLIT; nb += TN) {
        __syncthreads();
        for (int idx = t; idx < TN * C; idx += 256) {
            int n = idx & (TN - 1);
            int c = idx >> 6;
            uint32_t u = F[c * HW + nb + n];
            FcH[n * FSTR + c] = (unsigned short)u;
            FcL[n * FSTR + c] = (unsigned short)(u >> 16);
        }
        for (int idx = t; idx < CV * TN; idx += 256) {
            int n = idx & (TN - 1);
            int vc = idx >> 6;
            uint32_t u = g_V[(bb * CV + vc) * HW + nb + n];
            VsH[vc * VSTR + n] = (unsigned short)u;
            VsL[vc * VSTR + n] = (unsigned short)(u >> 16);
        }
        if (t < TN) r_c[t] = Rj[nb + t];
        __syncthreads();

        float4 acc[2][4];
#pragma unroll
        for (int mt = 0; mt < 2; mt++)
#pragma unroll
            for (int nt = 0; nt < 4; nt++) acc[mt][nt] = make_float4(0.f, 0.f, 0.f, 0.f);

#pragma unroll
        for (int kt = 0; kt < 4; kt++) {
            uint32_t AH[2][4], AL[2][4], BH[2][4], BL[2][4];
            ldsm_x4(AH[0][0], AH[0][1], AH[0][2], AH[0][3], aH0 + kt * 32);
            ldsm_x4(AH[1][0], AH[1][1], AH[1][2], AH[1][3], aH0 + kt * 32 + 16 * FSTR * 2);
            ldsm_x4(AL[0][0], AL[0][1], AL[0][2], AL[0][3], aL0 + kt * 32);
            ldsm_x4(AL[1][0], AL[1][1], AL[1][2], AL[1][3], aL0 + kt * 32 + 16 * FSTR * 2);
            ldsm_x4(BH[0][0], BH[0][1], BH[0][2], BH[0][3], bH0 + kt * 32);
            ldsm_x4(BH[1][0], BH[1][1], BH[1][2], BH[1][3], bH0 + kt * 32 + 16 * FSTR * 2);
            ldsm_x4(BL[0][0], BL[0][1], BL[0][2], BL[0][3], bL0 + kt * 32);
            ldsm_x4(BL[1][0], BL[1][1], BL[1][2], BL[1][3], bL0 + kt * 32 + 16 * FSTR * 2);
#pragma unroll
            for (int mt = 0; mt < 2; mt++) {
#pragma unroll
                for (int nt = 0; nt < 4; nt++) {
                    int np = nt >> 1, e = (nt & 1) * 2;
                    mma16816(acc[mt][nt], AH[mt], BH[np][e], BH[np][e + 1]);
                    mma16816(acc[mt][nt], AH[mt], BL[np][e], BL[np][e + 1]);
                    mma16816(acc[mt][nt], AL[mt], BH[np][e], BH[np][e + 1]);
                    mma16816(acc[mt][nt], AL[mt], BL[np][e], BL[np][e + 1]);
                }
            }
        }

#pragma unroll
        for (int nt = 0; nt < 4; nt++) {
            float rc0 = r_c[n0w + nt * 8 + qp * 2];
            float rc1 = r_c[n0w + nt * 8 + qp * 2 + 1];
#pragma unroll
            for (int mt = 0; mt < 2; mt++) {
                float4& a4 = acc[mt][nt];
                a4.x = __expf(-fmaxf(rr0[mt] + rc0 - 2.f * a4.x, 0.f) * inv2s);
                a4.y = __expf(-fmaxf(rr0[mt] + rc1 - 2.f * a4.y, 0.f) * inv2s);
                a4.z = __expf(-fmaxf(rr1[mt] + rc0 - 2.f * a4.z, 0.f) * inv2s);
                a4.w = __expf(-fmaxf(rr1[mt] + rc1 - 2.f * a4.w, 0.f) * inv2s);
            }
        }

#pragma unroll
        for (int kt = 0; kt < 4; kt++) {
            uint32_t ah0[2], ah1[2], al0[2], al1[2];
#pragma unroll
            for (int mt = 0; mt < 2; mt++) {
                split_pair(acc[mt][kt].x, acc[mt][kt].y, ah0[mt], al0[mt]);
                split_pair(acc[mt][kt].z, acc[mt][kt].w, ah1[mt], al1[mt]);
            }
#pragma unroll
            for (int vt = 0; vt < 3; vt++) {
                int vo = vbase + (vt * 8 * VSTR + kt * 8) * 2;
                uint32_t bh = *(const uint32_t*)((char*)(sm + OFF_VSTH) + vo);
                uint32_t bl = *(const uint32_t*)((char*)(sm + OFF_VSTL) + vo);
#pragma unroll
                for (int mt = 0; mt < 2; mt++) {
                    mma16808(O[mt][vt], ah0[mt], ah1[mt], bh);
                    mma16808(O[mt][vt], ah0[mt], ah1[mt], bl);
                    mma16808(O[mt][vt], al0[mt], al1[mt], bh);
                }
            }
        }
    }

    __syncthreads();
    float* Osh = (float*)sm;
    if (ng == 1) {
#pragma unroll
        for (int mt = 0; mt < 2; mt++)
#pragma unroll
            for (int vt = 0; vt < 3; vt++) {
                int r0 = m0w + mt * 16 + g;
                int c0 = vt * 8 + qp * 2;
                Osh[r0 * CV + c0] = O[mt][vt].x;
                Osh[r0 * CV + c0 + 1] = O[mt][vt].y;
                Osh[(r0 + 8) * CV + c0] = O[mt][vt].z;
                Osh[(r0 + 8) * CV + c0 + 1] = O[mt][vt].w;
            }
    }
    __syncthreads();
    if (ng == 0) {
        float* dst = g_O + ((size_t)((s * 12 + j * 4 + bb)) * HW + m0) * CV;
#pragma unroll
        for (int mt = 0; mt < 2; mt++)
#pragma unroll
            for (int vt = 0; vt < 3; vt++) {
                int r0 = m0w + mt * 16 + g;
                int c0 = vt * 8 + qp * 2;
                dst[r0 * CV + c0]           = O[mt][vt].x + Osh[r0 * CV + c0];
                dst[r0 * CV + c0 + 1]       = O[mt][vt].y + Osh[r0 * CV + c0 + 1];
                dst[(r0 + 8) * CV + c0]     = O[mt][vt].z + Osh[(r0 + 8) * CV + c0];
                dst[(r0 + 8) * CV + c0 + 1] = O[mt][vt].w + Osh[(r0 + 8) * CV + c0 + 1];
            }
    }
}

// ---------------------------------------------------------------------------
// 5) Combine: sum NSPLIT partial O slabs, mix, 1x1 out conv, gate, add edge
// ---------------------------------------------------------------------------
__global__ void combine_kernel(const float* __restrict__ Wo, const float* __restrict__ bo,
                               const float* __restrict__ gammas, float* __restrict__ out)
{
    __shared__ float wo_s[512];
    __shared__ float bo_s[64];
    int t = threadIdx.x;
    for (int i = t; i < 512; i += 256) wo_s[i] = Wo[i];
    if (t < 64) bo_s[t] = bo[t];
    __syncthreads();

    int k = blockIdx.y, b = blockIdx.z;
    int p = blockIdx.x * 256 + t;

    float g6 = gammas[6], g7 = gammas[7], g8 = gammas[8];
    float c1, c2, c3, gk;
    if (k == 0)      { c1 = g6;       c2 = g7 + 1.f; c3 = g8 + 1.f; gk = gammas[3]; }
    else if (k == 1) { c1 = g6 + 1.f; c2 = g7;       c3 = g8 + 1.f; gk = gammas[4]; }
    else             { c1 = g6 + 1.f; c2 = g7 + 1.f; c3 = g8;       gk = gammas[5]; }

    const size_t SLAB = (size_t)12 * HW * CV;
    float s0[8] = {0}, s1[8] = {0}, s2[8] = {0};
#pragma unroll
    for (int sp = 0; sp < NSPLIT; sp++) {
        const float* O0 = g_O + sp * SLAB + ((size_t)(0 + b) * HW + p) * CV + k * 8;
        const float* O1 = g_O + sp * SLAB + ((size_t)(4 + b) * HW + p) * CV + k * 8;
        const float* O2 = g_O + sp * SLAB + ((size_t)(8 + b) * HW + p) * CV + k * 8;
#pragma unroll
        for (int c = 0; c < 8; c++) { s0[c] += O0[c]; s1[c] += O1[c]; s2[c] += O2[c]; }
    }
    float att[8];
#pragma unroll
    for (int c = 0; c < 8; c++)
        att[c] = gk * (c1 * s0[c] + c2 * s1[c] + c3 * s2[c]);

    float e = g_edge[b * HW + p];
    const uint32_t* F = g_fpF + (k * 4 + b) * C * HW + p;
    float* op = out + k * NPIX + b * C * HW + p;
#pragma unroll 4
    for (int co = 0; co < C; co++) {
        float y = bo_s[co];
#pragma unroll
        for (int c = 0; c < 8; c++) y += wo_s[co * 8 + c] * att[c];
        op[co * HW] = unpack_f(F[co * HW]) * y + e;
    }
}

// ---------------------------------------------------------------------------
// Host launcher (graph-capturable)
// ---------------------------------------------------------------------------
extern "C" void kernel_launch(void* const* d_in, const int* in_sizes, int n_in,
                              void* d_out, int out_size)
{
    const float* x1    = (const float*)d_in[0];
    const float* x2    = (const float*)d_in[1];
    const float* x3    = (const float*)d_in[2];
    const float* Wc1   = (const float*)d_in[3];
    const float* bc1   = (const float*)d_in[4];
    const float* Wc2   = (const float*)d_in[5];
    const float* bc2   = (const float*)d_in[6];
    const float* Wc3   = (const float*)d_in[7];
    const float* bc3   = (const float*)d_in[8];
    const float* bnf_g = (const float*)d_in[9];
    const float* bnf_b = (const float*)d_in[10];
    const float* bnf_m = (const float*)d_in[11];
    const float* bnf_v = (const float*)d_in[12];
    const float* Wm    = (const float*)d_in[13];
    const float* bm    = (const float*)d_in[14];
    const float* bnm_g = (const float*)d_in[15];
    const float* bnm_b = (const float*)d_in[16];
    const float* bnm_m = (const float*)d_in[17];
    const float* bnm_v = (const float*)d_in[18];
    const float* Wv    = (const float*)d_in[19];
    const float* bv    = (const float*)d_in[20];
    const float* Wo    = (const float*)d_in[21];
    const float* bo    = (const float*)d_in[22];
    const float* gam   = (const float*)d_in[23];
    float* out = (float*)d_out;

    uint32_t *fp1, *fpF;
    cudaGetSymbolAddress((void**)&fp1, g_fp1);
    cudaGetSymbolAddress((void**)&fpF, g_fpF);

    cudaFuncSetAttribute(attn_kernel, cudaFuncAttributeMaxDynamicSharedMemorySize,
                         ATTN_SMEM_BYTES);
    cudaFuncSetAttribute(conv1_tc_kernel, cudaFuncAttributeMaxDynamicSharedMemorySize,
                         CONV_SMEM_BYTES);
    cudaFuncSetAttribute(convm0_kernel, cudaFuncAttributeMaxDynamicSharedMemorySize,
                         CONV_SMEM_BYTES);
    cudaFuncSetAttribute(convm1_kernel, cudaFuncAttributeMaxDynamicSharedMemorySize,
                         CONV_SMEM_BYTES);

    init_kernel<<<1335, 256>>>(Wm, Wc1, Wc2, Wc3, x3,
                               bc1, bc2, bc3, bnf_g, bnf_b, bnf_m, bnf_v,
                               bm, bnm_g, bnm_b, bnm_m, bnm_v);

    conv1_tc_kernel<<<dim3(12, 12, 3), 256, CONV_SMEM_BYTES>>>(x1, x2, x3, fp1);
    convm0_kernel<<<dim3(12, 12, 2), 256, CONV_SMEM_BYTES>>>(fp1);
    convm1_kernel<<<dim3(12, 12, 2), 256, CONV_SMEM_BYTES>>>();
    fixupF_kernel<<<3 * NPIX / 256, 256>>>(fpF);

    valr_kernel<<<dim3(9, 3, B), 256>>>(Wv, bv);
    attn_kernel<<<dim3((HW / TM) * NSPLIT, 3, B), 256, ATTN_SMEM_BYTES>>>(gam);
    combine_kernel<<<dim3(9, 3, B), 256>>>(Wo, bo, gam, out);
}

// round 16
// speedup vs baseline: 1.1438x; 1.1438x over previous
#include <cuda_runtime.h>
#include <cuda_bf16.h>
#include <math.h>
#include <stdint.h>

// ---------------------------------------------------------------------------
// Problem constants
// ---------------------------------------------------------------------------
#define B 4
#define C 64
#define IMGH 48
#define IMGW 48
#define HW 2304                 // 48*48
#define NPIX 589824             // B*C*HW
#define CV 24                   // 3 * (C/8) value columns
#define NSPLIT 4

// first-layer padded cin per branch and weight buffer offsets
#define CIN1P 144
#define CIN2P 32
#define CIN3P 16
#define W1OFF 0
#define W2OFF (9 * 64 * CIN1P)
#define W3OFF (9 * 64 * (CIN1P + CIN2P))
#define WCTOT (9 * 64 * (CIN1P + CIN2P + CIN3P))

// ---------------------------------------------------------------------------
// Device scratch (no cudaMalloc allowed)
// Features stored PACKED: uint32 = (hi bf16) | (lo bf16 << 16)
// ---------------------------------------------------------------------------
__device__ uint32_t g_fp1[3 * NPIX];            // layer-1 out (br1/br2 packed)
__device__ uint32_t g_fpF[3 * NPIX];            // final features
__device__ float g_pA[3 * NPIX];                // partial sums (conv1-br0 / convm1)
__device__ float g_pB[3 * NPIX];
__device__ float g_pC[NPIX];                    // third partial (conv1 x1 only)
__device__ float g_pD[3 * NPIX];                // convm0 partials
__device__ float g_pE[3 * NPIX];
__device__ float g_r[12 * HW];                  // [3][B][2304]
__device__ uint32_t g_V[B * CV * HW];           // [B][24][HW] packed hi/lo
__device__ float g_O[NSPLIT * 12 * HW * CV];    // [split][3][B][2304][24]
__device__ float g_edge[B * HW];
__device__ float g_scale[9 * 64];
__device__ float g_shift[9 * 64];
// mid-conv weights pre-split to bf16 hi/lo, layout [wi][tap][cout][cin]
__device__ __align__(16) __nv_bfloat16 g_WH[6 * 9 * 64 * 64];
__device__ __align__(16) __nv_bfloat16 g_WL[6 * 9 * 64 * 64];
// first-layer weights, layout [tap][cout][cin_pad] per branch
__device__ __align__(16) __nv_bfloat16 g_WcH[WCTOT];
__device__ __align__(16) __nv_bfloat16 g_WcL[WCTOT];

// ---------------------------------------------------------------------------
// helpers
// ---------------------------------------------------------------------------
__device__ __forceinline__ void ldsm_x4(uint32_t& r0, uint32_t& r1, uint32_t& r2,
                                        uint32_t& r3, uint32_t addr)
{
    asm volatile("ldmatrix.sync.aligned.m8n8.x4.shared.b16 {%0,%1,%2,%3}, [%4];"
                 : "=r"(r0), "=r"(r1), "=r"(r2), "=r"(r3) : "r"(addr));
}

__device__ __forceinline__ void mma16816(float4& d, const uint32_t a[4],
                                         uint32_t b0, uint32_t b1)
{
    asm volatile(
        "mma.sync.aligned.m16n8k16.row.col.f32.bf16.bf16.f32 "
        "{%0,%1,%2,%3}, {%4,%5,%6,%7}, {%8,%9}, {%0,%1,%2,%3};\n"
        : "+f"(d.x), "+f"(d.y), "+f"(d.z), "+f"(d.w)
        : "r"(a[0]), "r"(a[1]), "r"(a[2]), "r"(a[3]), "r"(b0), "r"(b1));
}

__device__ __forceinline__ void mma16808(float4& d, uint32_t a0, uint32_t a1, uint32_t b0)
{
    asm volatile(
        "mma.sync.aligned.m16n8k8.row.col.f32.bf16.bf16.f32 "
        "{%0,%1,%2,%3}, {%4,%5}, {%6}, {%0,%1,%2,%3};\n"
        : "+f"(d.x), "+f"(d.y), "+f"(d.z), "+f"(d.w)
        : "r"(a0), "r"(a1), "r"(b0));
}

__device__ __forceinline__ void split_pair(float x, float y, uint32_t& hi, uint32_t& lo)
{
    __nv_bfloat16 hx = __float2bfloat16(x);
    __nv_bfloat16 hy = __float2bfloat16(y);
    hi = (uint32_t)__bfloat16_as_ushort(hx) | ((uint32_t)__bfloat16_as_ushort(hy) << 16);
    __nv_bfloat16 lx = __float2bfloat16(x - __bfloat162float(hx));
    __nv_bfloat16 ly = __float2bfloat16(y - __bfloat162float(hy));
    lo = (uint32_t)__bfloat16_as_ushort(lx) | ((uint32_t)__bfloat16_as_ushort(ly) << 16);
}

__device__ __forceinline__ uint32_t pack_hl(float y)
{
    __nv_bfloat16 h = __float2bfloat16(y);
    __nv_bfloat16 l = __float2bfloat16(y - __bfloat162float(h));
    return (uint32_t)__bfloat16_as_ushort(h) | ((uint32_t)__bfloat16_as_ushort(l) << 16);
}

__device__ __forceinline__ float unpack_f(uint32_t u)
{
    return __uint_as_float(u << 16) + __uint_as_float(u & 0xFFFF0000u);
}

__device__ __forceinline__ uint32_t ld32(const __nv_bfloat16* p)
{
    return *(const uint32_t*)p;
}

__device__ __forceinline__ float leaky(float y) { return (y > 0.f) ? y : 0.01f * y; }

// ---------------------------------------------------------------------------
// 0) One merged init kernel: BN fold + both weight splits + sobel edge
// ---------------------------------------------------------------------------
__global__ void init_kernel(const float* __restrict__ Wm,
                            const float* __restrict__ Wc1,
                            const float* __restrict__ Wc2,
                            const float* __restrict__ Wc3,
                            const float* __restrict__ x3,
                            const float* __restrict__ bc1, const float* __restrict__ bc2,
                            const float* __restrict__ bc3,
                            const float* __restrict__ bnf_g, const float* __restrict__ bnf_b,
                            const float* __restrict__ bnf_m, const float* __restrict__ bnf_v,
                            const float* __restrict__ bm,
                            const float* __restrict__ bnm_g, const float* __restrict__ bnm_b,
                            const float* __restrict__ bnm_m, const float* __restrict__ bnm_v)
{
    const int bx = blockIdx.x;
    const int t = threadIdx.x;
    if (bx < 864) {
        int idx = bx * 256 + t;
        int cin = idx & 63;
        int r = idx >> 6;
        int cout = r & 63;
        r >>= 6;
        int tap = r % 9;
        int wi = r / 9;
        float x = Wm[((wi * 64 + cout) * 64 + cin) * 9 + tap];
        __nv_bfloat16 h = __float2bfloat16(x);
        g_WH[idx] = h;
        g_WL[idx] = __float2bfloat16(x - __bfloat162float(h));
    } else if (bx < 1296) {
        int idx = (bx - 864) * 256 + t;
        const float* W;
        int cinp, cin_real, rem;
        if (idx < W2OFF)       { W = Wc1; cinp = CIN1P; cin_real = 144; rem = idx - W1OFF; }
        else if (idx < W3OFF)  { W = Wc2; cinp = CIN2P; cin_real = 21;  rem = idx - W2OFF; }
        else                   { W = Wc3; cinp = CIN3P; cin_real = 1;   rem = idx - W3OFF; }
        int cin = rem % cinp;
        int r = rem / cinp;
        int cout = r & 63;
        int tap = r >> 6;
        float x = 0.f;
        if (cin < cin_real)
            x = W[(cout * cin_real + cin) * 9 + tap];
        __nv_bfloat16 h = __float2bfloat16(x);
        g_WcH[idx] = h;
        g_WcL[idx] = __float2bfloat16(x - __bfloat162float(h));
    } else if (bx < 1332) {
        int idx = (bx - 1296) * 256 + t;
        if (idx >= B * HW) return;
        int b = idx / HW, p = idx % HW;
        int h = p / IMGW, w = p % IMGW;
        const float* X = x3 + b * HW;
        float ex = 0.f, ey = 0.f;
        const float KX[9] = {-1.f, 0.f, 1.f, -2.f, 0.f, 2.f, -1.f, 0.f, 1.f};
        const float KY[9] = {-1.f, -2.f, -1.f, 0.f, 0.f, 0.f, 1.f, 2.f, 1.f};
#pragma unroll
        for (int kh = 0; kh < 3; kh++) {
            int gh = h + kh - 1;
            if (gh < 0 || gh >= IMGH) continue;
#pragma unroll
            for (int kw = 0; kw < 3; kw++) {
                int gw = w + kw - 1;
                if (gw < 0 || gw >= IMGW) continue;
                float xv = X[gh * IMGW + gw];
                ex += xv * KX[kh * 3 + kw];
                ey += xv * KY[kh * 3 + kw];
            }
        }
        g_edge[idx] = sqrtf(ex * ex + ey * ey);
    } else {
        int idx = (bx - 1332) * 256 + t;
        if (idx >= 576) return;
        int bi = idx >> 6, c = idx & 63;
        float bias, g, be, m, v;
        if (bi < 3) {
            bias = (bi == 0) ? bc1[c] : (bi == 1) ? bc2[c] : bc3[c];
            g = bnf_g[bi * 64 + c]; be = bnf_b[bi * 64 + c];
            m = bnf_m[bi * 64 + c]; v = bnf_v[bi * 64 + c];
        } else {
            int r = bi - 3;
            bias = bm[r * 64 + c];
            g = bnm_g[r * 64 + c]; be = bnm_b[r * 64 + c];
            m = bnm_m[r * 64 + c]; v = bnm_v[r * 64 + c];
        }
        float s = g * rsqrtf(v + 1e-5f);
        g_scale[idx] = s;
        g_shift[idx] = (bias - m) * s + be;
    }
}

// ---------------------------------------------------------------------------
// 2) Tensor-core 3x3 conv body (m32 tile, ldmatrix A, STS.128 weights).
//    Input MODE: 0=fp32 raw input (conv1), 1=packed u32, 2=sum3+BN, 3=sum2+BN.
//    RAW_OUT=true -> fp32 partial output; false -> fused BN+leaky+packed.
// ---------------------------------------------------------------------------
#define CINP 18
#define WSTR 24
#define CS_IMG_H 0
#define CS_IMG_L 5400                        // 300 * 18
#define CS_W_H   10800
#define CS_W_L   (10800 + 9 * 64 * WSTR)     // 24624
#define CS_ELEMS (CS_W_L + 9 * 64 * WSTR)    // 38448
#define CONV_SMEM_BYTES (CS_ELEMS * 2)       // 76896

template<int MODE, bool RAW_OUT>
__device__ __forceinline__ void conv_tc_body(const void* __restrict__ in0,
                                             const void* __restrict__ in1,
                                             const void* __restrict__ in2,
                                             const __nv_bfloat16* __restrict__ WHsrc,
                                             const __nv_bfloat16* __restrict__ WLsrc,
                                             int cin_stride, int cin_count, int cin_real,
                                             int bn_stage_base,   // g_scale offset for staging BN
                                             int bn_out,
                                             void* __restrict__ outv)
{
    extern __shared__ __align__(16) char csraw[];
    __nv_bfloat16* cs = (__nv_bfloat16*)csraw;
    __nv_bfloat16* imgH = cs + CS_IMG_H;
    __nv_bfloat16* imgL = cs + CS_IMG_L;
    __nv_bfloat16* wsH  = cs + CS_W_H;
    __nv_bfloat16* wsL  = cs + CS_W_L;
    const uint32_t sbase = (uint32_t)__cvta_generic_to_shared(csraw);

    const int strip = blockIdx.x;
    const int r0 = strip * 4;
    const int t = threadIdx.x;
    const int lane = t & 31, warp = t >> 5;
    const int wm = warp & 1;
    const int wn = warp >> 1;
    const int gq = lane >> 2, qp = lane & 3;

    float4 acc[2][6];
#pragma unroll
    for (int mt = 0; mt < 2; mt++)
#pragma unroll
        for (int nt = 0; nt < 6; nt++) acc[mt][nt] = make_float4(0.f, 0.f, 0.f, 0.f);

    const int bbase = (wn * 50 + gq) * CINP + 2 * qp;

    const int a_row = (lane & 7) + ((lane >> 3) & 1) * 8;
    const int a_col = ((lane >> 4) & 1) * 8;
    const uint32_t aH0 = sbase + (uint32_t)(CS_W_H + (wm * 32 + a_row) * WSTR + a_col) * 2;
    const uint32_t aL0 = aH0 + (uint32_t)(CS_W_L - CS_W_H) * 2;

    const int p0 = t;
    const int p1 = t + 256;
    const int r_0 = p0 / 50, cc_0 = p0 % 50;
    const int r_1 = p1 / 50, cc_1 = p1 % 50;

    for (int c0 = 0; c0 < cin_count; c0 += 16) {
        __syncthreads();

        // ---- stage image chunk ----
#pragma unroll
        for (int pp = 0; pp < 2; pp++) {
            int pos = pp ? p1 : p0;
            if (pp && p1 >= 300) break;
            int rr = pp ? r_1 : r_0, cc = pp ? cc_1 : cc_0;
            int gr = r0 + rr - 1, gc = cc - 1;
            bool valid = (gr >= 0 && gr < IMGH && gc >= 0 && gc < IMGW);
            int a = pos * CINP;
            size_t goff = (size_t)c0 * HW + gr * IMGW + gc;
            if (MODE == 1) {
                const uint32_t* src = (const uint32_t*)in0 + goff;
                uint32_t u[16];
#pragma unroll
                for (int ci = 0; ci < 16; ci++)
                    u[ci] = valid ? src[ci * HW] : 0u;
#pragma unroll
                for (int ci = 0; ci < 16; ci += 2) {
                    *(uint32_t*)(imgH + a + ci) = __byte_perm(u[ci], u[ci + 1], 0x5410);
                    *(uint32_t*)(imgL + a + ci) = __byte_perm(u[ci], u[ci + 1], 0x7632);
                }
            } else {
                const float* s0 = (const float*)in0 + goff;
                const float* s1 = (const float*)in1 + goff;
                const float* s2 = (const float*)in2 + goff;
                float v[16];
#pragma unroll
                for (int ci = 0; ci < 16; ci++) {
                    if (MODE == 0) {
                        bool ok = valid && (c0 + ci) < cin_real;
                        v[ci] = ok ? s0[ci * HW] : 0.f;
                    } else if (MODE == 2) {
                        v[ci] = valid ? (s0[ci * HW] + s1[ci * HW] + s2[ci * HW]) : 0.f;
                    } else { // MODE 3
                        v[ci] = valid ? (s0[ci * HW] + s1[ci * HW]) : 0.f;
                    }
                }
                if (MODE >= 2) {
#pragma unroll
                    for (int ci = 0; ci < 16; ci++) {
                        float sc = g_scale[bn_stage_base + c0 + ci];
                        float sh = g_shift[bn_stage_base + c0 + ci];
                        v[ci] = valid ? leaky(v[ci] * sc + sh) : 0.f;
                    }
                }
#pragma unroll
                for (int ci = 0; ci < 16; ci += 2) {
                    uint32_t h2, l2;
                    split_pair(v[ci], v[ci + 1], h2, l2);
                    *(uint32_t*)(imgH + a + ci) = h2;
                    *(uint32_t*)(imgL + a + ci) = l2;
                }
            }
        }

        // ---- stage weight chunk: LDG.128 -> STS.128 ----
        for (int q = t; q < 2304; q += 256) {
            int seg = q & 1;
            int plane = (q >> 1) & 1;
            int row = q >> 2;
            const __nv_bfloat16* src = (plane ? WLsrc : WHsrc)
                                       + (size_t)row * cin_stride + c0 + seg * 8;
            __nv_bfloat16* dst = (plane ? wsL : wsH) + row * WSTR + seg * 8;
            *(float4*)dst = *(const float4*)src;
        }
        __syncthreads();

        // ---- 9 tap-GEMMs, k16 each, m32 per warp; A via ldmatrix ----
        for (int tap = 0; tap < 9; tap++) {
            const int tpos = (tap / 3) * 50 + (tap % 3);
            uint32_t Ah[2][4], Al[2][4];
#pragma unroll
            for (int mt = 0; mt < 2; mt++) {
                uint32_t off = (uint32_t)((tap * 64 + mt * 16) * WSTR) * 2;
                ldsm_x4(Ah[mt][0], Ah[mt][1], Ah[mt][2], Ah[mt][3], aH0 + off);
                ldsm_x4(Al[mt][0], Al[mt][1], Al[mt][2], Al[mt][3], aL0 + off);
            }
#pragma unroll
            for (int nt = 0; nt < 6; nt++) {
                int ba = bbase + tpos * CINP + nt * 8 * CINP;
                uint32_t bh0 = ld32(imgH + ba);
                uint32_t bh1 = ld32(imgH + ba + 8);
                uint32_t bl0 = ld32(imgL + ba);
                uint32_t bl1 = ld32(imgL + ba + 8);
#pragma unroll
                for (int mt = 0; mt < 2; mt++) {
                    mma16816(acc[mt][nt], Ah[mt], bh0, bh1);
                    mma16816(acc[mt][nt], Ah[mt], bl0, bl1);
                    mma16816(acc[mt][nt], Al[mt], bh0, bh1);
                }
            }
        }
    }

    // ---- epilogue ----
#pragma unroll
    for (int mt = 0; mt < 2; mt++) {
        int cout0 = wm * 32 + mt * 16 + gq;
        int cout1 = cout0 + 8;
        if (RAW_OUT) {
            float* out = (float*)outv;
#pragma unroll
            for (int nt = 0; nt < 6; nt++) {
                int ocol = nt * 8 + 2 * qp;
                float4 a = acc[mt][nt];
                float* o0 = out + cout0 * HW + (r0 + wn) * IMGW + ocol;
                *(float2*)o0 = make_float2(a.x, a.y);
                *(float2*)(o0 + 8 * HW) = make_float2(a.z, a.w);
            }
        } else {
            uint32_t* out = (uint32_t*)outv;
            float s0 = g_scale[bn_out * 64 + cout0], sh0 = g_shift[bn_out * 64 + cout0];
            float s1 = g_scale[bn_out * 64 + cout1], sh1 = g_shift[bn_out * 64 + cout1];
#pragma unroll
            for (int nt = 0; nt < 6; nt++) {
                int ocol = nt * 8 + 2 * qp;
                float4 a = acc[mt][nt];
                float y0 = leaky(a.x * s0 + sh0);
                float y1 = leaky(a.y * s0 + sh0);
                float y2 = leaky(a.z * s1 + sh1);
                float y3 = leaky(a.w * s1 + sh1);
                uint32_t* o0 = out + cout0 * HW + (r0 + wn) * IMGW + ocol;
                *(uint2*)o0 = make_uint2(pack_hl(y0), pack_hl(y1));
                *(uint2*)(o0 + 8 * HW) = make_uint2(pack_hl(y2), pack_hl(y3));
            }
        }
    }
}

// First layer.  grid (12, 12, 3).
//   br=0 (x1, cin 144): cin-split x3 (z = split), RAW partials -> g_pA/B/C
//   br=1,2: z==0 only, fused BN+pack path -> g_fp1
__global__ __launch_bounds__(256, 2) void conv1_tc_kernel(const float* __restrict__ x1,
                                                          const float* __restrict__ x2,
                                                          const float* __restrict__ x3,
                                                          uint32_t* __restrict__ outbase)
{
    const int zb = blockIdx.y;
    const int b = zb & 3, br = zb >> 2;
    const int z = blockIdx.z;
    if (br == 0) {
        float* part = (z == 0) ? g_pA : (z == 1) ? g_pB : g_pC;
        conv_tc_body<0, true>(x1 + (size_t)b * 144 * HW + (size_t)z * 48 * HW, 0, 0,
                              g_WcH + W1OFF + z * 48, g_WcL + W1OFF + z * 48,
                              CIN1P, 48, 48, 0, 0,
                              part + (size_t)b * C * HW);
    } else if (br == 1) {
        if (z != 0) return;
        conv_tc_body<0, false>(x2 + (size_t)b * 21 * HW, 0, 0,
                               g_WcH + W2OFF, g_WcL + W2OFF,
                               CIN2P, CIN2P, 21, 0, 1,
                               outbase + 1 * NPIX + (size_t)b * C * HW);
    } else {
        if (z != 0) return;
        conv_tc_body<0, false>(x3 + (size_t)b * 1 * HW, 0, 0,
                               g_WcH + W3OFF, g_WcL + W3OFF,
                               CIN3P, CIN3P, 1, 0, 2,
                               outbase + 2 * NPIX + (size_t)b * C * HW);
    }
}

// Mid layer 0: fuses the conv1 fixup into staging.
//   br0 stages sum3(pA,pB,pC)+BN(0); br1/2 stage packed fp1.  -> g_pD/g_pE
__global__ __launch_bounds__(256, 2) void convm0_kernel(const uint32_t* __restrict__ fp1)
{
    const int zb = blockIdx.y;
    const int b = zb & 3, br = zb >> 2;
    const int z = blockIdx.z;
    const int wi = br * 2;
    float* part = (z == 0) ? g_pD : g_pE;
    size_t io = (size_t)br * NPIX + (size_t)b * C * HW + (size_t)z * 32 * HW;
    size_t po = (size_t)b * C * HW + (size_t)z * 32 * HW;   // br0 partials are [B][64][HW]
    if (br == 0) {
        conv_tc_body<2, true>(g_pA + po, g_pB + po, g_pC + po,
                              g_WH + (size_t)wi * 576 * 64 + z * 32,
                              g_WL + (size_t)wi * 576 * 64 + z * 32,
                              64, 32, 32, 0 * 64 + z * 32, 0,
                              part + (size_t)br * NPIX + (size_t)b * C * HW);
    } else {
        conv_tc_body<1, true>(fp1 + io, 0, 0,
                              g_WH + (size_t)wi * 576 * 64 + z * 32,
                              g_WL + (size_t)wi * 576 * 64 + z * 32,
                              64, 32, 32, 0, 0,
                              part + (size_t)br * NPIX + (size_t)b * C * HW);
    }
}

// Mid layer 1: fuses layer-0 fixup into staging (sum2(pD,pE)+BN(3+br*2)).
//   -> g_pA/g_pB partials
__global__ __launch_bounds__(256, 2) void convm1_kernel()
{
    const int zb = blockIdx.y;
    const int b = zb & 3, br = zb >> 2;
    const int z = blockIdx.z;
    const int wi = br * 2 + 1;
    float* part = (z == 0) ? g_pA : g_pB;
    size_t io = (size_t)br * NPIX + (size_t)b * C * HW + (size_t)z * 32 * HW;
    conv_tc_body<3, true>(g_pD + io, g_pE + io, 0,
                          g_WH + (size_t)wi * 576 * 64 + z * 32,
                          g_WL + (size_t)wi * 576 * 64 + z * 32,
                          64, 32, 32, (3 + br * 2) * 64 + z * 32, 0,
                          part + (size_t)br * NPIX + (size_t)b * C * HW);
}

// final fixup: fpF = pack(leaky(BN(pA+pB, 4+br*2)))
__global__ void fixupF_kernel(uint32_t* __restrict__ outbase)
{
    int idx = blockIdx.x * 256 + threadIdx.x;
    float v = g_pA[idx] + g_pB[idx];
    int br = idx / NPIX;
    int rem = idx - br * NPIX;
    int cout = (rem / HW) & 63;
    int bn = 4 + br * 2;
    float y = leaky(v * g_scale[bn * 64 + cout] + g_shift[bn * 64 + cout]);
    outbase[idx] = pack_hl(y);
}

// ---------------------------------------------------------------------------
// 3) squared norms + 1x1 value projection from packed features
// ---------------------------------------------------------------------------
__global__ void valr_kernel(const float* __restrict__ Wv, const float* __restrict__ bv)
{
    __shared__ float wv_s[512];   // [8][64]
    int t = threadIdx.x;
    int j = blockIdx.y, b = blockIdx.z;
    for (int i = t; i < 512; i += 256) wv_s[i] = Wv[i];
    __syncthreads();

    int p = blockIdx.x * 256 + t;
    const uint32_t* F = g_fpF + (j * 4 + b) * C * HW + p;
    float r = 0.f;
    float v[8] = {0, 0, 0, 0, 0, 0, 0, 0};
#pragma unroll 8
    for (int c = 0; c < C; c++) {
        float x = unpack_f(F[c * HW]);
        r += x * x;
#pragma unroll
        for (int cv = 0; cv < 8; cv++) v[cv] += wv_s[cv * 64 + c] * x;
    }
    g_r[(j * 4 + b) * HW + p] = r;
#pragma unroll
    for (int cv = 0; cv < 8; cv++)
        g_V[(b * CV + j * 8 + cv) * HW + p] = pack_hl(v[cv] + bv[cv]);
}

// ---------------------------------------------------------------------------
// 4) Tensor-core fused similarity-attention (bf16 split precision)
// ---------------------------------------------------------------------------
#define TM 128
#define TN 64
#define FSTR 72
#define VSTR 72
#define COLS_PER_SPLIT (HW / NSPLIT)

#define OFF_FRH 0
#define OFF_FRL (OFF_FRH + TM * FSTR * 2)            // 18432
#define OFF_FCH (OFF_FRL + TM * FSTR * 2)            // 36864
#define OFF_FCL (OFF_FCH + TN * FSTR * 2)            // 46080
#define OFF_VSTH (OFF_FCL + TN * FSTR * 2)           // 55296
#define OFF_VSTL (OFF_VSTH + CV * VSTR * 2)          // 58752
#define OFF_RR  (OFF_VSTL + CV * VSTR * 2)           // 62208
#define OFF_RC  (OFF_RR + TM * 4)                    // 62720
#define ATTN_SMEM_BYTES (OFF_RC + TN * 4)            // 62976

__global__ __launch_bounds__(256, 2) void attn_kernel(const float* __restrict__ gammas)
{
    extern __shared__ char sm[];
    unsigned short* FrH = (unsigned short*)(sm + OFF_FRH);
    unsigned short* FrL = (unsigned short*)(sm + OFF_FRL);
    unsigned short* FcH = (unsigned short*)(sm + OFF_FCH);
    unsigned short* FcL = (unsigned short*)(sm + OFF_FCL);
    unsigned short* VsH = (unsigned short*)(sm + OFF_VSTH);
    unsigned short* VsL = (unsigned short*)(sm + OFF_VSTL);
    float* r_r = (float*)(sm + OFF_RR);
    float* r_c = (float*)(sm + OFF_RC);
    uint32_t sb = (uint32_t)__cvta_generic_to_shared(sm);

    const int s    = blockIdx.x & (NSPLIT - 1);
    const int tile = blockIdx.x >> 2;                // log2(NSPLIT)=2
    const int j = blockIdx.y, bb = blockIdx.z;
    const int m0 = tile * TM;
    const int t = threadIdx.x;
    const int warp = t >> 5, lane = t & 31;
    const int mg = warp >> 1, ng = warp & 1;
    const int m0w = mg * 32, n0w = ng * 32;
    const int g = lane >> 2, qp = lane & 3;

    const uint32_t* F = g_fpF + (j * 4 + bb) * C * HW;
    const float* Rj = g_r + (j * 4 + bb) * HW;

    float sg = gammas[j];
    float inv2s = 1.0f / (2.0f * sg * sg);

    for (int idx = t; idx < TM * C; idx += 256) {
        int i = idx & (TM - 1);
        int c = idx >> 7;
        uint32_t u = F[c * HW + m0 + i];
        FrH[i * FSTR + c] = (unsigned short)u;
        FrL[i * FSTR + c] = (unsigned short)(u >> 16);
    }
    if (t < TM) r_r[t] = Rj[m0 + t];
    __syncthreads();

    float rr0[2], rr1[2];
#pragma unroll
    for (int mt = 0; mt < 2; mt++) {
        rr0[mt] = r_r[m0w + mt * 16 + g];
        rr1[mt] = r_r[m0w + mt * 16 + g + 8];
    }

    const int a_r = m0w + (lane & 7) + ((lane >> 3) & 1) * 8;
    const int a_c = ((lane >> 4) & 1) * 8;
    const uint32_t aH0 = sb + OFF_FRH + (uint32_t)(a_r * FSTR + a_c) * 2;
    const uint32_t aL0 = sb + OFF_FRL + (uint32_t)(a_r * FSTR + a_c) * 2;
    const int b_r = n0w + (lane & 7) + ((lane >> 4) & 1) * 8;
    const int b_c = ((lane >> 3) & 1) * 8;
    const uint32_t bH0 = sb + OFF_FCH + (uint32_t)(b_r * FSTR + b_c) * 2;
    const uint32_t bL0 = sb + OFF_FCL + (uint32_t)(b_r * FSTR + b_c) * 2;
    const int vbase = ((lane >> 2) * VSTR + n0w + qp * 2) * 2;

    float4 O[2][3];
#pragma unroll
    for (int mt = 0; mt < 2; mt++)
#pragma unroll
        for (int vt = 0; vt < 3; vt++) O[mt][vt] = make_float4(0.f, 0.f, 0.f, 0.f);

    const int nb0 = s * COLS_PER_SPLIT;
    for (int nb = nb0; nb < nb0 + COLS_PER_SPLIT; nb += TN) {
        __syncthreads();
        for (int idx = t; idx < TN * C; idx += 256) {
            int n = idx & (TN - 1);
            int c = idx >> 6;
            uint32_t u = F[c * HW + nb + n];
            FcH[n * FSTR + c] = (unsigned short)u;
            FcL[n * FSTR + c] = (unsigned short)(u >> 16);
        }
        for (int idx = t; idx < CV * TN; idx += 256) {
            int n = idx & (TN - 1);
            int vc = idx >> 6;
            uint32_t u = g_V[(bb * CV + vc) * HW + nb + n];
            VsH[vc * VSTR + n] = (unsigned short)u;
            VsL[vc * VSTR + n] = (unsigned short)(u >> 16);
        }
        if (t < TN) r_c[t] = Rj[nb + t];
        __syncthreads();

        float4 acc[2][4];
#pragma unroll
        for (int mt = 0; mt < 2; mt++)
#pragma unroll
            for (int nt = 0; nt < 4; nt++) acc[mt][nt] = make_float4(0.f, 0.f, 0.f, 0.f);

#pragma unroll
        for (int kt = 0; kt < 4; kt++) {
            uint32_t AH[2][4], AL[2][4], BH[2][4], BL[2][4];
            ldsm_x4(AH[0][0], AH[0][1], AH[0][2], AH[0][3], aH0 + kt * 32);
            ldsm_x4(AH[1][0], AH[1][1], AH[1][2], AH[1][3], aH0 + kt * 32 + 16 * FSTR * 2);
            ldsm_x4(AL[0][0], AL[0][1], AL[0][2], AL[0][3], aL0 + kt * 32);
            ldsm_x4(AL[1][0], AL[1][1], AL[1][2], AL[1][3], aL0 + kt * 32 + 16 * FSTR * 2);
            ldsm_x4(BH[0][0], BH[0][1], BH[0][2], BH[0][3], bH0 + kt * 32);
            ldsm_x4(BH[1][0], BH[1][1], BH[1][2], BH[1][3], bH0 + kt * 32 + 16 * FSTR * 2);
            ldsm_x4(BL[0][0], BL[0][1], BL[0][2], BL[0][3], bL0 + kt * 32);
            ldsm_x4(BL[1][0], BL[1][1], BL[1][2], BL[1][3], bL0 + kt * 32 + 16 * FSTR * 2);
#pragma unroll
            for (int mt = 0; mt < 2; mt++) {
#pragma unroll
                for (int nt = 0; nt < 4; nt++) {
                    int np = nt >> 1, e = (nt & 1) * 2;
                    mma16816(acc[mt][nt], AH[mt], BH[np][e], BH[np][e + 1]);
                    mma16816(acc[mt][nt], AH[mt], BL[np][e], BL[np][e + 1]);
                    mma16816(acc[mt][nt], AL[mt], BH[np][e], BH[np][e + 1]);
                    mma16816(acc[mt][nt], AL[mt], BL[np][e], BL[np][e + 1]);
                }
            }
        }

#pragma unroll
        for (int nt = 0; nt < 4; nt++) {
            float rc0 = r_c[n0w + nt * 8 + qp * 2];
            float rc1 = r_c[n0w + nt * 8 + qp * 2 + 1];
#pragma unroll
            for (int mt = 0; mt < 2; mt++) {
                float4& a4 = acc[mt][nt];
                a4.x = __expf(-fmaxf(rr0[mt] + rc0 - 2.f * a4.x, 0.f) * inv2s);
                a4.y = __expf(-fmaxf(rr0[mt] + rc1 - 2.f * a4.y, 0.f) * inv2s);
                a4.z = __expf(-fmaxf(rr1[mt] + rc0 - 2.f * a4.z, 0.f) * inv2s);
                a4.w = __expf(-fmaxf(rr1[mt] + rc1 - 2.f * a4.w, 0.f) * inv2s);
            }
        }

#pragma unroll
        for (int kt = 0; kt < 4; kt++) {
            uint32_t ah0[2], ah1[2], al0[2], al1[2];
#pragma unroll
            for (int mt = 0; mt < 2; mt++) {
                split_pair(acc[mt][kt].x, acc[mt][kt].y, ah0[mt], al0[mt]);
                split_pair(acc[mt][kt].z, acc[mt][kt].w, ah1[mt], al1[mt]);
            }
#pragma unroll
            for (int vt = 0; vt < 3; vt++) {
                int vo = vbase + (vt * 8 * VSTR + kt * 8) * 2;
                uint32_t bh = *(const uint32_t*)((char*)(sm + OFF_VSTH) + vo);
                uint32_t bl = *(const uint32_t*)((char*)(sm + OFF_VSTL) + vo);
#pragma unroll
                for (int mt = 0; mt < 2; mt++) {
                    mma16808(O[mt][vt], ah0[mt], ah1[mt], bh);
                    mma16808(O[mt][vt], ah0[mt], ah1[mt], bl);
                    mma16808(O[mt][vt], al0[mt], al1[mt], bh);
                }
            }
        }
    }

    __syncthreads();
    float* Osh = (float*)sm;
    if (ng == 1) {
#pragma unroll
        for (int mt = 0; mt < 2; mt++)
#pragma unroll
            for (int vt = 0; vt < 3; vt++) {
                int r0 = m0w + mt * 16 + g;
                int c0 = vt * 8 + qp * 2;
                Osh[r0 * CV + c0] = O[mt][vt].x;
                Osh[r0 * CV + c0 + 1] = O[mt][vt].y;
                Osh[(r0 + 8) * CV + c0] = O[mt][vt].z;
                Osh[(r0 + 8) * CV + c0 + 1] = O[mt][vt].w;
            }
    }
    __syncthreads();
    if (ng == 0) {
        float* dst = g_O + ((size_t)((s * 12 + j * 4 + bb)) * HW + m0) * CV;
#pragma unroll
        for (int mt = 0; mt < 2; mt++)
#pragma unroll
            for (int vt = 0; vt < 3; vt++) {
                int r0 = m0w + mt * 16 + g;
                int c0 = vt * 8 + qp * 2;
                dst[r0 * CV + c0]           = O[mt][vt].x + Osh[r0 * CV + c0];
                dst[r0 * CV + c0 + 1]       = O[mt][vt].y + Osh[r0 * CV + c0 + 1];
                dst[(r0 + 8) * CV + c0]     = O[mt][vt].z + Osh[(r0 + 8) * CV + c0];
                dst[(r0 + 8) * CV + c0 + 1] = O[mt][vt].w + Osh[(r0 + 8) * CV + c0 + 1];
            }
    }
}

// ---------------------------------------------------------------------------
// 5) Combine: sum NSPLIT partial O slabs, mix, 1x1 out conv, gate, add edge
// ---------------------------------------------------------------------------
__global__ void combine_kernel(const float* __restrict__ Wo, const float* __restrict__ bo,
                               const float* __restrict__ gammas, float* __restrict__ out)
{
    __shared__ float wo_s[512];
    __shared__ float bo_s[64];
    int t = threadIdx.x;
    for (int i = t; i < 512; i += 256) wo_s[i] = Wo[i];
    if (t < 64) bo_s[t] = bo[t];
    __syncthreads();

    int k = blockIdx.y, b = blockIdx.z;
    int p = blockIdx.x * 256 + t;

    float g6 = gammas[6], g7 = gammas[7], g8 = gammas[8];
    float c1, c2, c3, gk;
    if (k == 0)      { c1 = g6;       c2 = g7 + 1.f; c3 = g8 + 1.f; gk = gammas[3]; }
    else if (k == 1) { c1 = g6 + 1.f; c2 = g7;       c3 = g8 + 1.f; gk = gammas[4]; }
    else             { c1 = g6 + 1.f; c2 = g7 + 1.f; c3 = g8;       gk = gammas[5]; }

    const size_t SLAB = (size_t)12 * HW * CV;
    float s0[8] = {0}, s1[8] = {0}, s2[8] = {0};
#pragma unroll
    for (int sp = 0; sp < NSPLIT; sp++) {
        const float* O0 = g_O + sp * SLAB + ((size_t)(0 + b) * HW + p) * CV + k * 8;
        const float* O1 = g_O + sp * SLAB + ((size_t)(4 + b) * HW + p) * CV + k * 8;
        const float* O2 = g_O + sp * SLAB + ((size_t)(8 + b) * HW + p) * CV + k * 8;
#pragma unroll
        for (int c = 0; c < 8; c++) { s0[c] += O0[c]; s1[c] += O1[c]; s2[c] += O2[c]; }
    }
    float att[8];
#pragma unroll
    for (int c = 0; c < 8; c++)
        att[c] = gk * (c1 * s0[c] + c2 * s1[c] + c3 * s2[c]);

    float e = g_edge[b * HW + p];
    const uint32_t* F = g_fpF + (k * 4 + b) * C * HW + p;
    float* op = out + k * NPIX + b * C * HW + p;
#pragma unroll 4
    for (int co = 0; co < C; co++) {
        float y = bo_s[co];
#pragma unroll
        for (int c = 0; c < 8; c++) y += wo_s[co * 8 + c] * att[c];
        op[co * HW] = unpack_f(F[co * HW]) * y + e;
    }
}

// ---------------------------------------------------------------------------
// Host launcher (graph-capturable)
// ---------------------------------------------------------------------------
extern "C" void kernel_launch(void* const* d_in, const int* in_sizes, int n_in,
                              void* d_out, int out_size)
{
    const float* x1    = (const float*)d_in[0];
    const float* x2    = (const float*)d_in[1];
    const float* x3    = (const float*)d_in[2];
    const float* Wc1   = (const float*)d_in[3];
    const float* bc1   = (const float*)d_in[4];
    const float* Wc2   = (const float*)d_in[5];
    const float* bc2   = (const float*)d_in[6];
    const float* Wc3   = (const float*)d_in[7];
    const float* bc3   = (const float*)d_in[8];
    const float* bnf_g = (const float*)d_in[9];
    const float* bnf_b = (const float*)d_in[10];
    const float* bnf_m = (const float*)d_in[11];
    const float* bnf_v = (const float*)d_in[12];
    const float* Wm    = (const float*)d_in[13];
    const float* bm    = (const float*)d_in[14];
    const float* bnm_g = (const float*)d_in[15];
    const float* bnm_b = (const float*)d_in[16];
    const float* bnm_m = (const float*)d_in[17];
    const float* bnm_v = (const float*)d_in[18];
    const float* Wv    = (const float*)d_in[19];
    const float* bv    = (const float*)d_in[20];
    const float* Wo    = (const float*)d_in[21];
    const float* bo    = (const float*)d_in[22];
    const float* gam   = (const float*)d_in[23];
    float* out = (float*)d_out;

    uint32_t *fp1, *fpF;
    cudaGetSymbolAddress((void**)&fp1, g_fp1);
    cudaGetSymbolAddress((void**)&fpF, g_fpF);

    cudaFuncSetAttribute(attn_kernel, cudaFuncAttributeMaxDynamicSharedMemorySize,
                         ATTN_SMEM_BYTES);
    cudaFuncSetAttribute(conv1_tc_kernel, cudaFuncAttributeMaxDynamicSharedMemorySize,
                         CONV_SMEM_BYTES);
    cudaFuncSetAttribute(convm0_kernel, cudaFuncAttributeMaxDynamicSharedMemorySize,
                         CONV_SMEM_BYTES);
    cudaFuncSetAttribute(convm1_kernel, cudaFuncAttributeMaxDynamicSharedMemorySize,
                         CONV_SMEM_BYTES);

    init_kernel<<<1335, 256>>>(Wm, Wc1, Wc2, Wc3, x3,
                               bc1, bc2, bc3, bnf_g, bnf_b, bnf_m, bnf_v,
                               bm, bnm_g, bnm_b, bnm_m, bnm_v);

    conv1_tc_kernel<<<dim3(12, 12, 3), 256, CONV_SMEM_BYTES>>>(x1, x2, x3, fp1);
    convm0_kernel<<<dim3(12, 12, 2), 256, CONV_SMEM_BYTES>>>(fp1);
    convm1_kernel<<<dim3(12, 12, 2), 256, CONV_SMEM_BYTES>>>();
    fixupF_kernel<<<3 * NPIX / 256, 256>>>(fpF);

    valr_kernel<<<dim3(9, 3, B), 256>>>(Wv, bv);
    attn_kernel<<<dim3((HW / TM) * NSPLIT, 3, B), 256, ATTN_SMEM_BYTES>>>(gam);
    combine_kernel<<<dim3(9, 3, B), 256>>>(Wo, bo, gam, out);
}

// round 17
// speedup vs baseline: 1.1848x; 1.0359x over previous
#include <cuda_runtime.h>
#include <cuda_bf16.h>
#include <math.h>
#include <stdint.h>

// ---------------------------------------------------------------------------
// Problem constants
// ---------------------------------------------------------------------------
#define B 4
#define C 64
#define IMGH 48
#define IMGW 48
#define HW 2304                 // 48*48
#define NPIX 589824             // B*C*HW
#define CV 24                   // 3 * (C/8) value columns
#define NSPLIT 4

// first-layer padded cin per branch and weight buffer offsets
#define CIN1P 144
#define CIN2P 32
#define CIN3P 16
#define W1OFF 0
#define W2OFF (9 * 64 * CIN1P)
#define W3OFF (9 * 64 * (CIN1P + CIN2P))
#define WCTOT (9 * 64 * (CIN1P + CIN2P + CIN3P))

// ---------------------------------------------------------------------------
// Device scratch (no cudaMalloc allowed)
// Features stored PACKED: uint32 = (hi bf16) | (lo bf16 << 16)
// ---------------------------------------------------------------------------
__device__ uint32_t g_fp1[3 * NPIX];            // layer-1 out (br1/br2 packed)
__device__ uint32_t g_fpF[3 * NPIX];            // final features
__device__ float g_pA[3 * NPIX];                // partial sums (conv1-br0 / convm1)
__device__ float g_pB[3 * NPIX];
__device__ float g_pC[NPIX];                    // third partial (conv1 x1 only)
__device__ float g_pD[3 * NPIX];                // convm0 partials
__device__ float g_pE[3 * NPIX];
__device__ float g_r[12 * HW];                  // [3][B][2304]  CORRECTED norms (r - sum lo^2)
__device__ uint32_t g_V[B * CV * HW];           // [B][24][HW] packed hi/lo
__device__ float g_O[NSPLIT * 12 * HW * CV];    // [split][3][B][2304][24]
__device__ float g_edge[B * HW];
__device__ float g_scale[9 * 64];
__device__ float g_shift[9 * 64];
// mid-conv weights pre-split to bf16 hi/lo, layout [wi][tap][cout][cin]
__device__ __align__(16) __nv_bfloat16 g_WH[6 * 9 * 64 * 64];
__device__ __align__(16) __nv_bfloat16 g_WL[6 * 9 * 64 * 64];
// first-layer weights, layout [tap][cout][cin_pad] per branch
__device__ __align__(16) __nv_bfloat16 g_WcH[WCTOT];
__device__ __align__(16) __nv_bfloat16 g_WcL[WCTOT];

// ---------------------------------------------------------------------------
// helpers
// ---------------------------------------------------------------------------
__device__ __forceinline__ void ldsm_x4(uint32_t& r0, uint32_t& r1, uint32_t& r2,
                                        uint32_t& r3, uint32_t addr)
{
    asm volatile("ldmatrix.sync.aligned.m8n8.x4.shared.b16 {%0,%1,%2,%3}, [%4];"
                 : "=r"(r0), "=r"(r1), "=r"(r2), "=r"(r3) : "r"(addr));
}

__device__ __forceinline__ void mma16816(float4& d, const uint32_t a[4],
                                         uint32_t b0, uint32_t b1)
{
    asm volatile(
        "mma.sync.aligned.m16n8k16.row.col.f32.bf16.bf16.f32 "
        "{%0,%1,%2,%3}, {%4,%5,%6,%7}, {%8,%9}, {%0,%1,%2,%3};\n"
        : "+f"(d.x), "+f"(d.y), "+f"(d.z), "+f"(d.w)
        : "r"(a[0]), "r"(a[1]), "r"(a[2]), "r"(a[3]), "r"(b0), "r"(b1));
}

__device__ __forceinline__ void mma16808(float4& d, uint32_t a0, uint32_t a1, uint32_t b0)
{
    asm volatile(
        "mma.sync.aligned.m16n8k8.row.col.f32.bf16.bf16.f32 "
        "{%0,%1,%2,%3}, {%4,%5}, {%6}, {%0,%1,%2,%3};\n"
        : "+f"(d.x), "+f"(d.y), "+f"(d.z), "+f"(d.w)
        : "r"(a0), "r"(a1), "r"(b0));
}

__device__ __forceinline__ void split_pair(float x, float y, uint32_t& hi, uint32_t& lo)
{
    __nv_bfloat16 hx = __float2bfloat16(x);
    __nv_bfloat16 hy = __float2bfloat16(y);
    hi = (uint32_t)__bfloat16_as_ushort(hx) | ((uint32_t)__bfloat16_as_ushort(hy) << 16);
    __nv_bfloat16 lx = __float2bfloat16(x - __bfloat162float(hx));
    __nv_bfloat16 ly = __float2bfloat16(y - __bfloat162float(hy));
    lo = (uint32_t)__bfloat16_as_ushort(lx) | ((uint32_t)__bfloat16_as_ushort(ly) << 16);
}

__device__ __forceinline__ uint32_t pack_hl(float y)
{
    __nv_bfloat16 h = __float2bfloat16(y);
    __nv_bfloat16 l = __float2bfloat16(y - __bfloat162float(h));
    return (uint32_t)__bfloat16_as_ushort(h) | ((uint32_t)__bfloat16_as_ushort(l) << 16);
}

__device__ __forceinline__ float unpack_f(uint32_t u)
{
    return __uint_as_float(u << 16) + __uint_as_float(u & 0xFFFF0000u);
}

__device__ __forceinline__ uint32_t ld32(const __nv_bfloat16* p)
{
    return *(const uint32_t*)p;
}

__device__ __forceinline__ float leaky(float y) { return (y > 0.f) ? y : 0.01f * y; }

// ---------------------------------------------------------------------------
// 0) One merged init kernel: BN fold + both weight splits + sobel edge
// ---------------------------------------------------------------------------
__global__ void init_kernel(const float* __restrict__ Wm,
                            const float* __restrict__ Wc1,
                            const float* __restrict__ Wc2,
                            const float* __restrict__ Wc3,
                            const float* __restrict__ x3,
                            const float* __restrict__ bc1, const float* __restrict__ bc2,
                            const float* __restrict__ bc3,
                            const float* __restrict__ bnf_g, const float* __restrict__ bnf_b,
                            const float* __restrict__ bnf_m, const float* __restrict__ bnf_v,
                            const float* __restrict__ bm,
                            const float* __restrict__ bnm_g, const float* __restrict__ bnm_b,
                            const float* __restrict__ bnm_m, const float* __restrict__ bnm_v)
{
    const int bx = blockIdx.x;
    const int t = threadIdx.x;
    if (bx < 864) {
        int idx = bx * 256 + t;
        int cin = idx & 63;
        int r = idx >> 6;
        int cout = r & 63;
        r >>= 6;
        int tap = r % 9;
        int wi = r / 9;
        float x = Wm[((wi * 64 + cout) * 64 + cin) * 9 + tap];
        __nv_bfloat16 h = __float2bfloat16(x);
        g_WH[idx] = h;
        g_WL[idx] = __float2bfloat16(x - __bfloat162float(h));
    } else if (bx < 1296) {
        int idx = (bx - 864) * 256 + t;
        const float* W;
        int cinp, cin_real, rem;
        if (idx < W2OFF)       { W = Wc1; cinp = CIN1P; cin_real = 144; rem = idx - W1OFF; }
        else if (idx < W3OFF)  { W = Wc2; cinp = CIN2P; cin_real = 21;  rem = idx - W2OFF; }
        else                   { W = Wc3; cinp = CIN3P; cin_real = 1;   rem = idx - W3OFF; }
        int cin = rem % cinp;
        int r = rem / cinp;
        int cout = r & 63;
        int tap = r >> 6;
        float x = 0.f;
        if (cin < cin_real)
            x = W[(cout * cin_real + cin) * 9 + tap];
        __nv_bfloat16 h = __float2bfloat16(x);
        g_WcH[idx] = h;
        g_WcL[idx] = __float2bfloat16(x - __bfloat162float(h));
    } else if (bx < 1332) {
        int idx = (bx - 1296) * 256 + t;
        if (idx >= B * HW) return;
        int b = idx / HW, p = idx % HW;
        int h = p / IMGW, w = p % IMGW;
        const float* X = x3 + b * HW;
        float ex = 0.f, ey = 0.f;
        const float KX[9] = {-1.f, 0.f, 1.f, -2.f, 0.f, 2.f, -1.f, 0.f, 1.f};
        const float KY[9] = {-1.f, -2.f, -1.f, 0.f, 0.f, 0.f, 1.f, 2.f, 1.f};
#pragma unroll
        for (int kh = 0; kh < 3; kh++) {
            int gh = h + kh - 1;
            if (gh < 0 || gh >= IMGH) continue;
#pragma unroll
            for (int kw = 0; kw < 3; kw++) {
                int gw = w + kw - 1;
                if (gw < 0 || gw >= IMGW) continue;
                float xv = X[gh * IMGW + gw];
                ex += xv * KX[kh * 3 + kw];
                ey += xv * KY[kh * 3 + kw];
            }
        }
        g_edge[idx] = sqrtf(ex * ex + ey * ey);
    } else {
        int idx = (bx - 1332) * 256 + t;
        if (idx >= 576) return;
        int bi = idx >> 6, c = idx & 63;
        float bias, g, be, m, v;
        if (bi < 3) {
            bias = (bi == 0) ? bc1[c] : (bi == 1) ? bc2[c] : bc3[c];
            g = bnf_g[bi * 64 + c]; be = bnf_b[bi * 64 + c];
            m = bnf_m[bi * 64 + c]; v = bnf_v[bi * 64 + c];
        } else {
            int r = bi - 3;
            bias = bm[r * 64 + c];
            g = bnm_g[r * 64 + c]; be = bnm_b[r * 64 + c];
            m = bnm_m[r * 64 + c]; v = bnm_v[r * 64 + c];
        }
        float s = g * rsqrtf(v + 1e-5f);
        g_scale[idx] = s;
        g_shift[idx] = (bias - m) * s + be;
    }
}

// ---------------------------------------------------------------------------
// 2) Tensor-core 3x3 conv body (m32 tile, ldmatrix A, STS.128 weights).
//    Input MODE: 0=fp32 raw input (conv1), 1=packed u32, 2=sum3+BN, 3=sum2+BN.
//    RAW_OUT=true -> fp32 partial output; false -> fused BN+leaky+packed.
// ---------------------------------------------------------------------------
#define CINP 18
#define WSTR 24
#define CS_IMG_H 0
#define CS_IMG_L 5400                        // 300 * 18
#define CS_W_H   10800
#define CS_W_L   (10800 + 9 * 64 * WSTR)     // 24624
#define CS_ELEMS (CS_W_L + 9 * 64 * WSTR)    // 38448
#define CONV_SMEM_BYTES (CS_ELEMS * 2)       // 76896

template<int MODE, bool RAW_OUT>
__device__ __forceinline__ void conv_tc_body(const void* __restrict__ in0,
                                             const void* __restrict__ in1,
                                             const void* __restrict__ in2,
                                             const __nv_bfloat16* __restrict__ WHsrc,
                                             const __nv_bfloat16* __restrict__ WLsrc,
                                             int cin_stride, int cin_count, int cin_real,
                                             int bn_stage_base,   // g_scale offset for staging BN
                                             int bn_out,
                                             void* __restrict__ outv)
{
    extern __shared__ __align__(16) char csraw[];
    __nv_bfloat16* cs = (__nv_bfloat16*)csraw;
    __nv_bfloat16* imgH = cs + CS_IMG_H;
    __nv_bfloat16* imgL = cs + CS_IMG_L;
    __nv_bfloat16* wsH  = cs + CS_W_H;
    __nv_bfloat16* wsL  = cs + CS_W_L;
    const uint32_t sbase = (uint32_t)__cvta_generic_to_shared(csraw);

    const int strip = blockIdx.x;
    const int r0 = strip * 4;
    const int t = threadIdx.x;
    const int lane = t & 31, warp = t >> 5;
    const int wm = warp & 1;
    const int wn = warp >> 1;
    const int gq = lane >> 2, qp = lane & 3;

    float4 acc[2][6];
#pragma unroll
    for (int mt = 0; mt < 2; mt++)
#pragma unroll
        for (int nt = 0; nt < 6; nt++) acc[mt][nt] = make_float4(0.f, 0.f, 0.f, 0.f);

    const int bbase = (wn * 50 + gq) * CINP + 2 * qp;

    const int a_row = (lane & 7) + ((lane >> 3) & 1) * 8;
    const int a_col = ((lane >> 4) & 1) * 8;
    const uint32_t aH0 = sbase + (uint32_t)(CS_W_H + (wm * 32 + a_row) * WSTR + a_col) * 2;
    const uint32_t aL0 = aH0 + (uint32_t)(CS_W_L - CS_W_H) * 2;

    const int p0 = t;
    const int p1 = t + 256;
    const int r_0 = p0 / 50, cc_0 = p0 % 50;
    const int r_1 = p1 / 50, cc_1 = p1 % 50;

    for (int c0 = 0; c0 < cin_count; c0 += 16) {
        __syncthreads();

        // ---- stage image chunk ----
#pragma unroll
        for (int pp = 0; pp < 2; pp++) {
            int pos = pp ? p1 : p0;
            if (pp && p1 >= 300) break;
            int rr = pp ? r_1 : r_0, cc = pp ? cc_1 : cc_0;
            int gr = r0 + rr - 1, gc = cc - 1;
            bool valid = (gr >= 0 && gr < IMGH && gc >= 0 && gc < IMGW);
            int a = pos * CINP;
            size_t goff = (size_t)c0 * HW + gr * IMGW + gc;
            if (MODE == 1) {
                const uint32_t* src = (const uint32_t*)in0 + goff;
                uint32_t u[16];
#pragma unroll
                for (int ci = 0; ci < 16; ci++)
                    u[ci] = valid ? src[ci * HW] : 0u;
#pragma unroll
                for (int ci = 0; ci < 16; ci += 2) {
                    *(uint32_t*)(imgH + a + ci) = __byte_perm(u[ci], u[ci + 1], 0x5410);
                    *(uint32_t*)(imgL + a + ci) = __byte_perm(u[ci], u[ci + 1], 0x7632);
                }
            } else {
                const float* s0 = (const float*)in0 + goff;
                const float* s1 = (const float*)in1 + goff;
                const float* s2 = (const float*)in2 + goff;
                float v[16];
#pragma unroll
                for (int ci = 0; ci < 16; ci++) {
                    if (MODE == 0) {
                        bool ok = valid && (c0 + ci) < cin_real;
                        v[ci] = ok ? s0[ci * HW] : 0.f;
                    } else if (MODE == 2) {
                        v[ci] = valid ? (s0[ci * HW] + s1[ci * HW] + s2[ci * HW]) : 0.f;
                    } else { // MODE 3
                        v[ci] = valid ? (s0[ci * HW] + s1[ci * HW]) : 0.f;
                    }
                }
                if (MODE >= 2) {
#pragma unroll
                    for (int ci = 0; ci < 16; ci++) {
                        float sc = g_scale[bn_stage_base + c0 + ci];
                        float sh = g_shift[bn_stage_base + c0 + ci];
                        v[ci] = valid ? leaky(v[ci] * sc + sh) : 0.f;
                    }
                }
#pragma unroll
                for (int ci = 0; ci < 16; ci += 2) {
                    uint32_t h2, l2;
                    split_pair(v[ci], v[ci + 1], h2, l2);
                    *(uint32_t*)(imgH + a + ci) = h2;
                    *(uint32_t*)(imgL + a + ci) = l2;
                }
            }
        }

        // ---- stage weight chunk: LDG.128 -> STS.128 ----
        for (int q = t; q < 2304; q += 256) {
            int seg = q & 1;
            int plane = (q >> 1) & 1;
            int row = q >> 2;
            const __nv_bfloat16* src = (plane ? WLsrc : WHsrc)
                                       + (size_t)row * cin_stride + c0 + seg * 8;
            __nv_bfloat16* dst = (plane ? wsL : wsH) + row * WSTR + seg * 8;
            *(float4*)dst = *(const float4*)src;
        }
        __syncthreads();

        // ---- 9 tap-GEMMs, k16 each, m32 per warp; A via ldmatrix ----
        for (int tap = 0; tap < 9; tap++) {
            const int tpos = (tap / 3) * 50 + (tap % 3);
            uint32_t Ah[2][4], Al[2][4];
#pragma unroll
            for (int mt = 0; mt < 2; mt++) {
                uint32_t off = (uint32_t)((tap * 64 + mt * 16) * WSTR) * 2;
                ldsm_x4(Ah[mt][0], Ah[mt][1], Ah[mt][2], Ah[mt][3], aH0 + off);
                ldsm_x4(Al[mt][0], Al[mt][1], Al[mt][2], Al[mt][3], aL0 + off);
            }
#pragma unroll
            for (int nt = 0; nt < 6; nt++) {
                int ba = bbase + tpos * CINP + nt * 8 * CINP;
                uint32_t bh0 = ld32(imgH + ba);
                uint32_t bh1 = ld32(imgH + ba + 8);
                uint32_t bl0 = ld32(imgL + ba);
                uint32_t bl1 = ld32(imgL + ba + 8);
#pragma unroll
                for (int mt = 0; mt < 2; mt++) {
                    mma16816(acc[mt][nt], Ah[mt], bh0, bh1);
                    mma16816(acc[mt][nt], Ah[mt], bl0, bl1);
                    mma16816(acc[mt][nt], Al[mt], bh0, bh1);
                }
            }
        }
    }

    // ---- epilogue ----
#pragma unroll
    for (int mt = 0; mt < 2; mt++) {
        int cout0 = wm * 32 + mt * 16 + gq;
        int cout1 = cout0 + 8;
        if (RAW_OUT) {
            float* out = (float*)outv;
#pragma unroll
            for (int nt = 0; nt < 6; nt++) {
                int ocol = nt * 8 + 2 * qp;
                float4 a = acc[mt][nt];
                float* o0 = out + cout0 * HW + (r0 + wn) * IMGW + ocol;
                *(float2*)o0 = make_float2(a.x, a.y);
                *(float2*)(o0 + 8 * HW) = make_float2(a.z, a.w);
            }
        } else {
            uint32_t* out = (uint32_t*)outv;
            float s0 = g_scale[bn_out * 64 + cout0], sh0 = g_shift[bn_out * 64 + cout0];
            float s1 = g_scale[bn_out * 64 + cout1], sh1 = g_shift[bn_out * 64 + cout1];
#pragma unroll
            for (int nt = 0; nt < 6; nt++) {
                int ocol = nt * 8 + 2 * qp;
                float4 a = acc[mt][nt];
                float y0 = leaky(a.x * s0 + sh0);
                float y1 = leaky(a.y * s0 + sh0);
                float y2 = leaky(a.z * s1 + sh1);
                float y3 = leaky(a.w * s1 + sh1);
                uint32_t* o0 = out + cout0 * HW + (r0 + wn) * IMGW + ocol;
                *(uint2*)o0 = make_uint2(pack_hl(y0), pack_hl(y1));
                *(uint2*)(o0 + 8 * HW) = make_uint2(pack_hl(y2), pack_hl(y3));
            }
        }
    }
}

// First layer.  grid (12, 12, 3).
__global__ __launch_bounds__(256, 2) void conv1_tc_kernel(const float* __restrict__ x1,
                                                          const float* __restrict__ x2,
                                                          const float* __restrict__ x3,
                                                          uint32_t* __restrict__ outbase)
{
    const int zb = blockIdx.y;
    const int b = zb & 3, br = zb >> 2;
    const int z = blockIdx.z;
    if (br == 0) {
        float* part = (z == 0) ? g_pA : (z == 1) ? g_pB : g_pC;
        conv_tc_body<0, true>(x1 + (size_t)b * 144 * HW + (size_t)z * 48 * HW, 0, 0,
                              g_WcH + W1OFF + z * 48, g_WcL + W1OFF + z * 48,
                              CIN1P, 48, 48, 0, 0,
                              part + (size_t)b * C * HW);
    } else if (br == 1) {
        if (z != 0) return;
        conv_tc_body<0, false>(x2 + (size_t)b * 21 * HW, 0, 0,
                               g_WcH + W2OFF, g_WcL + W2OFF,
                               CIN2P, CIN2P, 21, 0, 1,
                               outbase + 1 * NPIX + (size_t)b * C * HW);
    } else {
        if (z != 0) return;
        conv_tc_body<0, false>(x3 + (size_t)b * 1 * HW, 0, 0,
                               g_WcH + W3OFF, g_WcL + W3OFF,
                               CIN3P, CIN3P, 1, 0, 2,
                               outbase + 2 * NPIX + (size_t)b * C * HW);
    }
}

// Mid layer 0: fuses the conv1 fixup into staging.
__global__ __launch_bounds__(256, 2) void convm0_kernel(const uint32_t* __restrict__ fp1)
{
    const int zb = blockIdx.y;
    const int b = zb & 3, br = zb >> 2;
    const int z = blockIdx.z;
    const int wi = br * 2;
    float* part = (z == 0) ? g_pD : g_pE;
    size_t io = (size_t)br * NPIX + (size_t)b * C * HW + (size_t)z * 32 * HW;
    size_t po = (size_t)b * C * HW + (size_t)z * 32 * HW;
    if (br == 0) {
        conv_tc_body<2, true>(g_pA + po, g_pB + po, g_pC + po,
                              g_WH + (size_t)wi * 576 * 64 + z * 32,
                              g_WL + (size_t)wi * 576 * 64 + z * 32,
                              64, 32, 32, 0 * 64 + z * 32, 0,
                              part + (size_t)br * NPIX + (size_t)b * C * HW);
    } else {
        conv_tc_body<1, true>(fp1 + io, 0, 0,
                              g_WH + (size_t)wi * 576 * 64 + z * 32,
                              g_WL + (size_t)wi * 576 * 64 + z * 32,
                              64, 32, 32, 0, 0,
                              part + (size_t)br * NPIX + (size_t)b * C * HW);
    }
}

// Mid layer 1: fuses layer-0 fixup into staging.
__global__ __launch_bounds__(256, 2) void convm1_kernel()
{
    const int zb = blockIdx.y;
    const int b = zb & 3, br = zb >> 2;
    const int z = blockIdx.z;
    const int wi = br * 2 + 1;
    float* part = (z == 0) ? g_pA : g_pB;
    size_t io = (size_t)br * NPIX + (size_t)b * C * HW + (size_t)z * 32 * HW;
    conv_tc_body<3, true>(g_pD + io, g_pE + io, 0,
                          g_WH + (size_t)wi * 576 * 64 + z * 32,
                          g_WL + (size_t)wi * 576 * 64 + z * 32,
                          64, 32, 32, (3 + br * 2) * 64 + z * 32, 0,
                          part + (size_t)br * NPIX + (size_t)b * C * HW);
}

// final fixup: fpF = pack(leaky(BN(pA+pB, 4+br*2)))
__global__ void fixupF_kernel(uint32_t* __restrict__ outbase)
{
    int idx = blockIdx.x * 256 + threadIdx.x;
    float v = g_pA[idx] + g_pB[idx];
    int br = idx / NPIX;
    int rem = idx - br * NPIX;
    int cout = (rem / HW) & 63;
    int bn = 4 + br * 2;
    float y = leaky(v * g_scale[bn * 64 + cout] + g_shift[bn * 64 + cout]);
    outbase[idx] = pack_hl(y);
}

// ---------------------------------------------------------------------------
// 3) corrected norms r' = sum(x^2 - lo^2) + 1x1 value projection
//    (r' makes the 3-pass Gram's d2 exactly 0 on the diagonal)
// ---------------------------------------------------------------------------
__global__ void valr_kernel(const float* __restrict__ Wv, const float* __restrict__ bv)
{
    __shared__ float wv_s[512];   // [8][64]
    int t = threadIdx.x;
    int j = blockIdx.y, b = blockIdx.z;
    for (int i = t; i < 512; i += 256) wv_s[i] = Wv[i];
    __syncthreads();

    int p = blockIdx.x * 256 + t;
    const uint32_t* F = g_fpF + (j * 4 + b) * C * HW + p;
    float r = 0.f;
    float v[8] = {0, 0, 0, 0, 0, 0, 0, 0};
#pragma unroll 8
    for (int c = 0; c < C; c++) {
        uint32_t u = F[c * HW];
        float x = unpack_f(u);
        float lo = __uint_as_float(u & 0xFFFF0000u);
        r += x * x - lo * lo;
#pragma unroll
        for (int cv = 0; cv < 8; cv++) v[cv] += wv_s[cv * 64 + c] * x;
    }
    g_r[(j * 4 + b) * HW + p] = r;
#pragma unroll
    for (int cv = 0; cv < 8; cv++)
        g_V[(b * CV + j * 8 + cv) * HW + p] = pack_hl(v[cv] + bv[cv]);
}

// ---------------------------------------------------------------------------
// 4) Tensor-core fused similarity-attention (bf16 split precision)
//    Gram: 3-pass (HH, HL, LH) + corrected norms -> exact diagonal
// ---------------------------------------------------------------------------
#define TM 128
#define TN 64
#define FSTR 72
#define VSTR 72
#define COLS_PER_SPLIT (HW / NSPLIT)

#define OFF_FRH 0
#define OFF_FRL (OFF_FRH + TM * FSTR * 2)            // 18432
#define OFF_FCH (OFF_FRL + TM * FSTR * 2)            // 36864
#define OFF_FCL (OFF_FCH + TN * FSTR * 2)            // 46080
#define OFF_VSTH (OFF_FCL + TN * FSTR * 2)           // 55296
#define OFF_VSTL (OFF_VSTH + CV * VSTR * 2)          // 58752
#define OFF_RR  (OFF_VSTL + CV * VSTR * 2)           // 62208
#define OFF_RC  (OFF_RR + TM * 4)                    // 62720
#define ATTN_SMEM_BYTES (OFF_RC + TN * 4)            // 62976

__global__ __launch_bounds__(256, 2) void attn_kernel(const float* __restrict__ gammas)
{
    extern __shared__ char sm[];
    unsigned short* FrH = (unsigned short*)(sm + OFF_FRH);
    unsigned short* FrL = (unsigned short*)(sm + OFF_FRL);
    unsigned short* FcH = (unsigned short*)(sm + OFF_FCH);
    unsigned short* FcL = (unsigned short*)(sm + OFF_FCL);
    unsigned short* VsH = (unsigned short*)(sm + OFF_VSTH);
    unsigned short* VsL = (unsigned short*)(sm + OFF_VSTL);
    float* r_r = (float*)(sm + OFF_RR);
    float* r_c = (float*)(sm + OFF_RC);
    uint32_t sb = (uint32_t)__cvta_generic_to_shared(sm);

    const int s    = blockIdx.x & (NSPLIT - 1);
    const int tile = blockIdx.x >> 2;                // log2(NSPLIT)=2
    const int j = blockIdx.y, bb = blockIdx.z;
    const int m0 = tile * TM;
    const int t = threadIdx.x;
    const int warp = t >> 5, lane = t & 31;
    const int mg = warp >> 1, ng = warp & 1;
    const int m0w = mg * 32, n0w = ng * 32;
    const int g = lane >> 2, qp = lane & 3;

    const uint32_t* F = g_fpF + (j * 4 + bb) * C * HW;
    const float* Rj = g_r + (j * 4 + bb) * HW;

    float sg = gammas[j];
    float inv2s = 1.0f / (2.0f * sg * sg);

    for (int idx = t; idx < TM * C; idx += 256) {
        int i = idx & (TM - 1);
        int c = idx >> 7;
        uint32_t u = F[c * HW + m0 + i];
        FrH[i * FSTR + c] = (unsigned short)u;
        FrL[i * FSTR + c] = (unsigned short)(u >> 16);
    }
    if (t < TM) r_r[t] = Rj[m0 + t];
    __syncthreads();

    float rr0[2], rr1[2];
#pragma unroll
    for (int mt = 0; mt < 2; mt++) {
        rr0[mt] = r_r[m0w + mt * 16 + g];
        rr1[mt] = r_r[m0w + mt * 16 + g + 8];
    }

    const int a_r = m0w + (lane & 7) + ((lane >> 3) & 1) * 8;
    const int a_c = ((lane >> 4) & 1) * 8;
    const uint32_t aH0 = sb + OFF_FRH + (uint32_t)(a_r * FSTR + a_c) * 2;
    const uint32_t aL0 = sb + OFF_FRL + (uint32_t)(a_r * FSTR + a_c) * 2;
    const int b_r = n0w + (lane & 7) + ((lane >> 4) & 1) * 8;
    const int b_c = ((lane >> 3) & 1) * 8;
    const uint32_t bH0 = sb + OFF_FCH + (uint32_t)(b_r * FSTR + b_c) * 2;
    const uint32_t bL0 = sb + OFF_FCL + (uint32_t)(b_r * FSTR + b_c) * 2;
    const int vbase = ((lane >> 2) * VSTR + n0w + qp * 2) * 2;

    float4 O[2][3];
#pragma unroll
    for (int mt = 0; mt < 2; mt++)
#pragma unroll
        for (int vt = 0; vt < 3; vt++) O[mt][vt] = make_float4(0.f, 0.f, 0.f, 0.f);

    const int nb0 = s * COLS_PER_SPLIT;
    for (int nb = nb0; nb < nb0 + COLS_PER_SPLIT; nb += TN) {
        __syncthreads();
        for (int idx = t; idx < TN * C; idx += 256) {
            int n = idx & (TN - 1);
            int c = idx >> 6;
            uint32_t u = F[c * HW + nb + n];
            FcH[n * FSTR + c] = (unsigned short)u;
            FcL[n * FSTR + c] = (unsigned short)(u >> 16);
        }
        for (int idx = t; idx < CV * TN; idx += 256) {
            int n = idx & (TN - 1);
            int vc = idx >> 6;
            uint32_t u = g_V[(bb * CV + vc) * HW + nb + n];
            VsH[vc * VSTR + n] = (unsigned short)u;
            VsL[vc * VSTR + n] = (unsigned short)(u >> 16);
        }
        if (t < TN) r_c[t] = Rj[nb + t];
        __syncthreads();

        float4 acc[2][4];
#pragma unroll
        for (int mt = 0; mt < 2; mt++)
#pragma unroll
            for (int nt = 0; nt < 4; nt++) acc[mt][nt] = make_float4(0.f, 0.f, 0.f, 0.f);

#pragma unroll
        for (int kt = 0; kt < 4; kt++) {
            uint32_t AH[2][4], AL[2][4], BH[2][4], BL[2][4];
            ldsm_x4(AH[0][0], AH[0][1], AH[0][2], AH[0][3], aH0 + kt * 32);
            ldsm_x4(AH[1][0], AH[1][1], AH[1][2], AH[1][3], aH0 + kt * 32 + 16 * FSTR * 2);
            ldsm_x4(AL[0][0], AL[0][1], AL[0][2], AL[0][3], aL0 + kt * 32);
            ldsm_x4(AL[1][0], AL[1][1], AL[1][2], AL[1][3], aL0 + kt * 32 + 16 * FSTR * 2);
            ldsm_x4(BH[0][0], BH[0][1], BH[0][2], BH[0][3], bH0 + kt * 32);
            ldsm_x4(BH[1][0], BH[1][1], BH[1][2], BH[1][3], bH0 + kt * 32 + 16 * FSTR * 2);
            ldsm_x4(BL[0][0], BL[0][1], BL[0][2], BL[0][3], bL0 + kt * 32);
            ldsm_x4(BL[1][0], BL[1][1], BL[1][2], BL[1][3], bL0 + kt * 32 + 16 * FSTR * 2);
#pragma unroll
            for (int mt = 0; mt < 2; mt++) {
#pragma unroll
                for (int nt = 0; nt < 4; nt++) {
                    int np = nt >> 1, e = (nt & 1) * 2;
                    mma16816(acc[mt][nt], AH[mt], BH[np][e], BH[np][e + 1]);
                    mma16816(acc[mt][nt], AH[mt], BL[np][e], BL[np][e + 1]);
                    mma16816(acc[mt][nt], AL[mt], BH[np][e], BH[np][e + 1]);
                }
            }
        }

#pragma unroll
        for (int nt = 0; nt < 4; nt++) {
            float rc0 = r_c[n0w + nt * 8 + qp * 2];
            float rc1 = r_c[n0w + nt * 8 + qp * 2 + 1];
#pragma unroll
            for (int mt = 0; mt < 2; mt++) {
                float4& a4 = acc[mt][nt];
                a4.x = __expf(-fmaxf(rr0[mt] + rc0 - 2.f * a4.x, 0.f) * inv2s);
                a4.y = __expf(-fmaxf(rr0[mt] + rc1 - 2.f * a4.y, 0.f) * inv2s);
                a4.z = __expf(-fmaxf(rr1[mt] + rc0 - 2.f * a4.z, 0.f) * inv2s);
                a4.w = __expf(-fmaxf(rr1[mt] + rc1 - 2.f * a4.w, 0.f) * inv2s);
            }
        }

#pragma unroll
        for (int kt = 0; kt < 4; kt++) {
            uint32_t ah0[2], ah1[2], al0[2], al1[2];
#pragma unroll
            for (int mt = 0; mt < 2; mt++) {
                split_pair(acc[mt][kt].x, acc[mt][kt].y, ah0[mt], al0[mt]);
                split_pair(acc[mt][kt].z, acc[mt][kt].w, ah1[mt], al1[mt]);
            }
#pragma unroll
            for (int vt = 0; vt < 3; vt++) {
                int vo = vbase + (vt * 8 * VSTR + kt * 8) * 2;
                uint32_t bh = *(const uint32_t*)((char*)(sm + OFF_VSTH) + vo);
                uint32_t bl = *(const uint32_t*)((char*)(sm + OFF_VSTL) + vo);
#pragma unroll
                for (int mt = 0; mt < 2; mt++) {
                    mma16808(O[mt][vt], ah0[mt], ah1[mt], bh);
                    mma16808(O[mt][vt], ah0[mt], ah1[mt], bl);
                    mma16808(O[mt][vt], al0[mt], al1[mt], bh);
                }
            }
        }
    }

    __syncthreads();
    float* Osh = (float*)sm;
    if (ng == 1) {
#pragma unroll
        for (int mt = 0; mt < 2; mt++)
#pragma unroll
            for (int vt = 0; vt < 3; vt++) {
                int r0 = m0w + mt * 16 + g;
                int c0 = vt * 8 + qp * 2;
                Osh[r0 * CV + c0] = O[mt][vt].x;
                Osh[r0 * CV + c0 + 1] = O[mt][vt].y;
                Osh[(r0 + 8) * CV + c0] = O[mt][vt].z;
                Osh[(r0 + 8) * CV + c0 + 1] = O[mt][vt].w;
            }
    }
    __syncthreads();
    if (ng == 0) {
        float* dst = g_O + ((size_t)((s * 12 + j * 4 + bb)) * HW + m0) * CV;
#pragma unroll
        for (int mt = 0; mt < 2; mt++)
#pragma unroll
            for (int vt = 0; vt < 3; vt++) {
                int r0 = m0w + mt * 16 + g;
                int c0 = vt * 8 + qp * 2;
                dst[r0 * CV + c0]           = O[mt][vt].x + Osh[r0 * CV + c0];
                dst[r0 * CV + c0 + 1]       = O[mt][vt].y + Osh[r0 * CV + c0 + 1];
                dst[(r0 + 8) * CV + c0]     = O[mt][vt].z + Osh[(r0 + 8) * CV + c0];
                dst[(r0 + 8) * CV + c0 + 1] = O[mt][vt].w + Osh[(r0 + 8) * CV + c0 + 1];
            }
    }
}

// ---------------------------------------------------------------------------
// 5) Combine: sum NSPLIT partial O slabs, mix, 1x1 out conv, gate, add edge
// ---------------------------------------------------------------------------
__global__ void combine_kernel(const float* __restrict__ Wo, const float* __restrict__ bo,
                               const float* __restrict__ gammas, float* __restrict__ out)
{
    __shared__ float wo_s[512];
    __shared__ float bo_s[64];
    int t = threadIdx.x;
    for (int i = t; i < 512; i += 256) wo_s[i] = Wo[i];
    if (t < 64) bo_s[t] = bo[t];
    __syncthreads();

    int k = blockIdx.y, b = blockIdx.z;
    int p = blockIdx.x * 256 + t;

    float g6 = gammas[6], g7 = gammas[7], g8 = gammas[8];
    float c1, c2, c3, gk;
    if (k == 0)      { c1 = g6;       c2 = g7 + 1.f; c3 = g8 + 1.f; gk = gammas[3]; }
    else if (k == 1) { c1 = g6 + 1.f; c2 = g7;       c3 = g8 + 1.f; gk = gammas[4]; }
    else             { c1 = g6 + 1.f; c2 = g7 + 1.f; c3 = g8;       gk = gammas[5]; }

    const size_t SLAB = (size_t)12 * HW * CV;
    float s0[8] = {0}, s1[8] = {0}, s2[8] = {0};
#pragma unroll
    for (int sp = 0; sp < NSPLIT; sp++) {
        const float* O0 = g_O + sp * SLAB + ((size_t)(0 + b) * HW + p) * CV + k * 8;
        const float* O1 = g_O + sp * SLAB + ((size_t)(4 + b) * HW + p) * CV + k * 8;
        const float* O2 = g_O + sp * SLAB + ((size_t)(8 + b) * HW + p) * CV + k * 8;
#pragma unroll
        for (int c = 0; c < 8; c++) { s0[c] += O0[c]; s1[c] += O1[c]; s2[c] += O2[c]; }
    }
    float att[8];
#pragma unroll
    for (int c = 0; c < 8; c++)
        att[c] = gk * (c1 * s0[c] + c2 * s1[c] + c3 * s2[c]);

    float e = g_edge[b * HW + p];
    const uint32_t* F = g_fpF + (k * 4 + b) * C * HW + p;
    float* op = out + k * NPIX + b * C * HW + p;
#pragma unroll 4
    for (int co = 0; co < C; co++) {
        float y = bo_s[co];
#pragma unroll
        for (int c = 0; c < 8; c++) y += wo_s[co * 8 + c] * att[c];
        op[co * HW] = unpack_f(F[co * HW]) * y + e;
    }
}

// ---------------------------------------------------------------------------
// Host launcher (graph-capturable)
// ---------------------------------------------------------------------------
extern "C" void kernel_launch(void* const* d_in, const int* in_sizes, int n_in,
                              void* d_out, int out_size)
{
    const float* x1    = (const float*)d_in[0];
    const float* x2    = (const float*)d_in[1];
    const float* x3    = (const float*)d_in[2];
    const float* Wc1   = (const float*)d_in[3];
    const float* bc1   = (const float*)d_in[4];
    const float* Wc2   = (const float*)d_in[5];
    const float* bc2   = (const float*)d_in[6];
    const float* Wc3   = (const float*)d_in[7];
    const float* bc3   = (const float*)d_in[8];
    const float* bnf_g = (const float*)d_in[9];
    const float* bnf_b = (const float*)d_in[10];
    const float* bnf_m = (const float*)d_in[11];
    const float* bnf_v = (const float*)d_in[12];
    const float* Wm    = (const float*)d_in[13];
    const float* bm    = (const float*)d_in[14];
    const float* bnm_g = (const float*)d_in[15];
    const float* bnm_b = (const float*)d_in[16];
    const float* bnm_m = (const float*)d_in[17];
    const float* bnm_v = (const float*)d_in[18];
    const float* Wv    = (const float*)d_in[19];
    const float* bv    = (const float*)d_in[20];
    const float* Wo    = (const float*)d_in[21];
    const float* bo    = (const float*)d_in[22];
    const float* gam   = (const float*)d_in[23];
    float* out = (float*)d_out;

    uint32_t *fp1, *fpF;
    cudaGetSymbolAddress((void**)&fp1, g_fp1);
    cudaGetSymbolAddress((void**)&fpF, g_fpF);

    cudaFuncSetAttribute(attn_kernel, cudaFuncAttributeMaxDynamicSharedMemorySize,
                         ATTN_SMEM_BYTES);
    cudaFuncSetAttribute(conv1_tc_kernel, cudaFuncAttributeMaxDynamicSharedMemorySize,
                         CONV_SMEM_BYTES);
    cudaFuncSetAttribute(convm0_kernel, cudaFuncAttributeMaxDynamicSharedMemorySize,
                         CONV_SMEM_BYTES);
    cudaFuncSetAttribute(convm1_kernel, cudaFuncAttributeMaxDynamicSharedMemorySize,
                         CONV_SMEM_BYTES);

    init_kernel<<<1335, 256>>>(Wm, Wc1, Wc2, Wc3, x3,
                               bc1, bc2, bc3, bnf_g, bnf_b, bnf_m, bnf_v,
                               bm, bnm_g, bnm_b, bnm_m, bnm_v);

    conv1_tc_kernel<<<dim3(12, 12, 3), 256, CONV_SMEM_BYTES>>>(x1, x2, x3, fp1);
    convm0_kernel<<<dim3(12, 12, 2), 256, CONV_SMEM_BYTES>>>(fp1);
    convm1_kernel<<<dim3(12, 12, 2), 256, CONV_SMEM_BYTES>>>();
    fixupF_kernel<<<3 * NPIX / 256, 256>>>(fpF);

    valr_kernel<<<dim3(9, 3, B), 256>>>(Wv, bv);
    attn_kernel<<<dim3((HW / TM) * NSPLIT, 3, B), 256, ATTN_SMEM_BYTES>>>(gam);
    combine_kernel<<<dim3(9, 3, B), 256>>>(Wo, bo, gam, out);
}